// round 1
// baseline (speedup 1.0000x reference)
#include <cuda_runtime.h>
#include <math.h>

#define NB 2048

// ---------------- scratch (device globals; no allocation) ----------------
__device__ float g_h1[NB * 20 * 16 * 28];   // conv1+pool out  [b][20][16][28]
__device__ float g_h2[NB * 50 * 6 * 12];    // conv2+pool out  [b][50][6][12]
__device__ float g_p [NB * 16 * 72];        // pcaps conv out  [b][16][72]
__device__ float g_c [NB * 2];              // routed capsule outputs
__device__ float g_f1[NB * 500];            // fc1 relu out
__device__ float g_w2r[500 * 52];           // conv2 w relaid: [k=ic*25+kr*5+kc][oc pad 52]
__device__ float g_wpr[1250 * 16];          // pcaps w relaid: [k=ic*25+kr*5+kc][oc 16]

// ---------------- prep: weight relayout ----------------
__global__ void prep_k(const float* __restrict__ w2, const float* __restrict__ wp) {
    int i = blockIdx.x * blockDim.x + threadIdx.x;
    if (i < 500 * 52) {
        int k = i / 52, oc = i % 52;
        g_w2r[i] = (oc < 50) ? w2[oc * 500 + k] : 0.f;
    }
    if (i < 1250 * 16) {
        int k = i / 16, oc = i % 16;
        g_wpr[i] = wp[oc * 1250 + k];
    }
}

// ---------------- conv1 (1->20, 5x5 valid) + 2x2 maxpool ----------------
// in [36,60] -> conv [20,32,56] -> pool [20,16,28]
__global__ __launch_bounds__(256) void conv1_pool_k(
    const float* __restrict__ x, const float* __restrict__ w, const float* __restrict__ bias) {
    __shared__ __align__(16) float sx[36 * 60];
    __shared__ float sw[500];
    __shared__ float sb[20];
    int b = blockIdx.x;
    for (int i = threadIdx.x; i < 2160; i += 256) sx[i] = x[b * 2160 + i];
    for (int i = threadIdx.x; i < 500;  i += 256) sw[i] = w[i];
    if (threadIdx.x < 20) sb[threadIdx.x] = bias[threadIdx.x];
    __syncthreads();
    for (int i = threadIdx.x; i < 8960; i += 256) {
        int oc = i / 448, rem = i % 448, ph = rem / 28, pw = rem % 28;
        int r0 = ph * 2, c0 = pw * 2;
        float patch[6][6];
#pragma unroll
        for (int pr = 0; pr < 6; pr++) {
            const float2* row = (const float2*)&sx[(r0 + pr) * 60 + c0];
            float2 p0 = row[0], p1 = row[1], p2 = row[2];
            patch[pr][0] = p0.x; patch[pr][1] = p0.y;
            patch[pr][2] = p1.x; patch[pr][3] = p1.y;
            patch[pr][4] = p2.x; patch[pr][5] = p2.y;
        }
        const float* wp = &sw[oc * 25];
        float a00 = 0, a01 = 0, a10 = 0, a11 = 0;
#pragma unroll
        for (int kr = 0; kr < 5; kr++)
#pragma unroll
            for (int kc = 0; kc < 5; kc++) {
                float wv = wp[kr * 5 + kc];
                a00 = fmaf(patch[kr][kc],     wv, a00);
                a01 = fmaf(patch[kr][kc + 1], wv, a01);
                a10 = fmaf(patch[kr + 1][kc],     wv, a10);
                a11 = fmaf(patch[kr + 1][kc + 1], wv, a11);
            }
        g_h1[b * 8960 + i] = fmaxf(fmaxf(a00, a01), fmaxf(a10, a11)) + sb[oc];
    }
}

// ---------------- conv2 (20->50, 5x5 valid) + 2x2 maxpool ----------------
// in [20,16,28] -> conv [50,12,24] -> pool [50,6,12]
// dyn smem: sx 8960 floats + sconv 52*288 floats
__global__ __launch_bounds__(256) void conv2_pool_k(const float* __restrict__ bias) {
    extern __shared__ __align__(16) float smem2[];
    float* sx = smem2;            // 8960
    float* sconv = smem2 + 8960;  // 52*288 = 14976
    int b = blockIdx.x;
    for (int i = threadIdx.x; i < 8960; i += 256) sx[i] = g_h1[b * 8960 + i];
    __syncthreads();
    // tiles: 13 oc-groups(4) x 12 conv rows x 3 col-groups(8) = 468
    for (int t = threadIdx.x; t < 468; t += 256) {
        int og = t / 36, rem = t % 36, r = rem / 3, cg = rem % 3;
        int oc0 = og * 4, c0 = cg * 8;
        float acc0[8] = {}, acc1[8] = {}, acc2[8] = {}, acc3[8] = {};
        for (int ic = 0; ic < 20; ic++) {
#pragma unroll
            for (int kr = 0; kr < 5; kr++) {
                const float* xrow = &sx[ic * 448 + (r + kr) * 28 + c0];
                float4 xa = *(const float4*)xrow;
                float4 xb = *(const float4*)(xrow + 4);
                float4 xc = *(const float4*)(xrow + 8);
                float xr[12] = {xa.x, xa.y, xa.z, xa.w, xb.x, xb.y, xb.z, xb.w,
                                xc.x, xc.y, xc.z, xc.w};
                int krow = ic * 25 + kr * 5;
#pragma unroll
                for (int kc = 0; kc < 5; kc++) {
                    float4 wv = *(const float4*)&g_w2r[(krow + kc) * 52 + oc0];
#pragma unroll
                    for (int p = 0; p < 8; p++) {
                        float xv = xr[kc + p];
                        acc0[p] = fmaf(xv, wv.x, acc0[p]);
                        acc1[p] = fmaf(xv, wv.y, acc1[p]);
                        acc2[p] = fmaf(xv, wv.z, acc2[p]);
                        acc3[p] = fmaf(xv, wv.w, acc3[p]);
                    }
                }
            }
        }
#pragma unroll
        for (int p = 0; p < 8; p++) {
            sconv[(oc0 + 0) * 288 + r * 24 + c0 + p] = acc0[p];
            sconv[(oc0 + 1) * 288 + r * 24 + c0 + p] = acc1[p];
            sconv[(oc0 + 2) * 288 + r * 24 + c0 + p] = acc2[p];
            sconv[(oc0 + 3) * 288 + r * 24 + c0 + p] = acc3[p];
        }
    }
    __syncthreads();
    for (int i = threadIdx.x; i < 3600; i += 256) {
        int oc = i / 72, rem = i % 72, ph = rem / 12, pw = rem % 12;
        const float* base = &sconv[oc * 288 + ph * 48 + pw * 2];
        float m = fmaxf(fmaxf(base[0], base[1]), fmaxf(base[24], base[25]));
        g_h2[b * 3600 + i] = m + bias[oc];
    }
}

// ---------------- primary caps conv (50->16, 5x5 pad 2) ----------------
// 2 images/block, zero-padded smem [2][50][10][16], per-thread 2oc x 6cols
__global__ __launch_bounds__(192) void pcaps_k(const float* __restrict__ bias) {
    extern __shared__ __align__(16) float sxp[];  // 16000 floats
    int b0 = blockIdx.x * 2;
    for (int i = threadIdx.x; i < 16000; i += 192) sxp[i] = 0.f;
    __syncthreads();
    for (int i = threadIdx.x; i < 7200; i += 192) {
        int img = i / 3600, idx = i % 3600;
        int ic = idx / 72, rem = idx % 72, h = rem / 12, w = rem % 12;
        sxp[((img * 50 + ic) * 10 + h + 2) * 16 + w + 2] = g_h2[(b0 + img) * 3600 + idx];
    }
    __syncthreads();
    int t = threadIdx.x;
    int img = t / 96, q = t % 96;
    int rr = q / 16; q &= 15;
    int cg = q >> 3, og = q & 7;
    int oc0 = og * 2, c0 = cg * 6;
    float accA[6] = {}, accB[6] = {};
    for (int ic = 0; ic < 50; ic++) {
#pragma unroll
        for (int kr = 0; kr < 5; kr++) {
            const float* xrow = &sxp[((img * 50 + ic) * 10 + rr + kr) * 16 + c0];
            float xr[10];
#pragma unroll
            for (int s = 0; s < 10; s++) xr[s] = xrow[s];
            int krow = ic * 25 + kr * 5;
#pragma unroll
            for (int kc = 0; kc < 5; kc++) {
                float2 wv = *(const float2*)&g_wpr[(krow + kc) * 16 + oc0];
#pragma unroll
                for (int j = 0; j < 6; j++) {
                    float xv = xr[kc + j];
                    accA[j] = fmaf(xv, wv.x, accA[j]);
                    accB[j] = fmaf(xv, wv.y, accB[j]);
                }
            }
        }
    }
    float bA = bias[oc0], bB = bias[oc0 + 1];
    int obase = (b0 + img) * 1152 + rr * 12 + c0;
#pragma unroll
    for (int j = 0; j < 6; j++) {
        g_p[obase + oc0 * 72 + j]       = accA[j] + bA;
        g_p[obase + (oc0 + 1) * 72 + j] = accB[j] + bB;
    }
}

// ---------------- squash + priors + 3-iter dynamic routing ----------------
// one warp per (b, k); 288 route nodes = 32 lanes x 9
__device__ __forceinline__ float sq1(float s) { return s * fabsf(s) / (1.f + s * s); }

__global__ __launch_bounds__(256) void routing_k(const float* __restrict__ rw) {
    int warp = (blockIdx.x * blockDim.x + threadIdx.x) >> 5;
    int lane = threadIdx.x & 31;
    int b = warp >> 1, k = warp & 1;
    float pr[9];
#pragma unroll
    for (int j = 0; j < 9; j++) {
        int r = lane + 32 * j;
        int cw = r / 72, hw = r % 72;
        const float* pb = g_p + b * 1152 + cw * 72 + hw;
        float u0 = pb[0], u1 = pb[288], u2 = pb[576], u3 = pb[864];
        float n2 = u0 * u0 + u1 * u1 + u2 * u2 + u3 * u3;
        float f = sqrtf(n2) / (1.f + n2);   // squash scale
        float4 w4 = *(const float4*)&rw[(k * 288 + r) * 4];
        pr[j] = f * (u0 * w4.x + u1 * w4.y + u2 * w4.z + u3 * w4.w);
    }
    // iter 0: uniform probs
    float S = 0.f;
#pragma unroll
    for (int j = 0; j < 9; j++) S += pr[j];
#pragma unroll
    for (int o = 16; o; o >>= 1) S += __shfl_xor_sync(0xffffffffu, S, o);
    float s = S * (1.f / 288.f);
    float v = sq1(s);
    float vsum = v;
#pragma unroll
    for (int it = 0; it < 2; it++) {
        float m = -1e30f;
#pragma unroll
        for (int j = 0; j < 9; j++) m = fmaxf(m, pr[j] * vsum);
#pragma unroll
        for (int o = 16; o; o >>= 1) m = fmaxf(m, __shfl_xor_sync(0xffffffffu, m, o));
        float Z = 0.f, T = 0.f;
#pragma unroll
        for (int j = 0; j < 9; j++) {
            float e = __expf(pr[j] * vsum - m);
            Z += e;
            T = fmaf(e, pr[j], T);
        }
#pragma unroll
        for (int o = 16; o; o >>= 1) {
            Z += __shfl_xor_sync(0xffffffffu, Z, o);
            T += __shfl_xor_sync(0xffffffffu, T, o);
        }
        float s2 = T / Z;
        v = sq1(s2);
        vsum += v;
    }
    if (lane == 0) g_c[b * 2 + k] = v;
}

// ---------------- fc1: relu([h2 | c] @ W1^T + b1), M=2048 N=500 K=3602 ----------------
__global__ __launch_bounds__(256) void fc1_k(const float* __restrict__ W, const float* __restrict__ bias) {
    __shared__ float As[16][64];
    __shared__ float Bs[16][68];
    int m0 = blockIdx.y * 64, n0 = blockIdx.x * 64;
    int tid = threadIdx.x;
    int lr = tid >> 2;         // 0..63
    int lk = (tid & 3) * 4;    // 0,4,8,12
    int tx = tid & 15, ty = tid >> 4;
    float acc[4][4] = {};
    for (int k0 = 0; k0 < 3602; k0 += 16) {
        // A tile
        if (k0 + 16 <= 3600) {
            float4 v = *(const float4*)&g_h2[(m0 + lr) * 3600 + k0 + lk];
            As[lk + 0][lr] = v.x; As[lk + 1][lr] = v.y;
            As[lk + 2][lr] = v.z; As[lk + 3][lr] = v.w;
        } else {
#pragma unroll
            for (int q = 0; q < 4; q++) {
                int kk = k0 + lk + q;
                float v = 0.f;
                if (kk < 3600) v = g_h2[(m0 + lr) * 3600 + kk];
                else if (kk < 3602) v = g_c[(m0 + lr) * 2 + (kk - 3600)];
                As[lk + q][lr] = v;
            }
        }
        // B tile (W rows = n)
        {
            int n = n0 + lr;
#pragma unroll
            for (int q = 0; q < 4; q++) {
                int kk = k0 + lk + q;
                Bs[lk + q][lr] = (n < 500 && kk < 3602) ? W[n * 3602 + kk] : 0.f;
            }
        }
        __syncthreads();
#pragma unroll
        for (int kk = 0; kk < 16; kk++) {
            float4 a = *(const float4*)&As[kk][ty * 4];
            float4 bq = *(const float4*)&Bs[kk][tx * 4];
            acc[0][0] = fmaf(a.x, bq.x, acc[0][0]); acc[0][1] = fmaf(a.x, bq.y, acc[0][1]);
            acc[0][2] = fmaf(a.x, bq.z, acc[0][2]); acc[0][3] = fmaf(a.x, bq.w, acc[0][3]);
            acc[1][0] = fmaf(a.y, bq.x, acc[1][0]); acc[1][1] = fmaf(a.y, bq.y, acc[1][1]);
            acc[1][2] = fmaf(a.y, bq.z, acc[1][2]); acc[1][3] = fmaf(a.y, bq.w, acc[1][3]);
            acc[2][0] = fmaf(a.z, bq.x, acc[2][0]); acc[2][1] = fmaf(a.z, bq.y, acc[2][1]);
            acc[2][2] = fmaf(a.z, bq.z, acc[2][2]); acc[2][3] = fmaf(a.z, bq.w, acc[2][3]);
            acc[3][0] = fmaf(a.w, bq.x, acc[3][0]); acc[3][1] = fmaf(a.w, bq.y, acc[3][1]);
            acc[3][2] = fmaf(a.w, bq.z, acc[3][2]); acc[3][3] = fmaf(a.w, bq.w, acc[3][3]);
        }
        __syncthreads();
    }
#pragma unroll
    for (int i = 0; i < 4; i++)
#pragma unroll
        for (int j = 0; j < 4; j++) {
            int n = n0 + tx * 4 + j;
            if (n < 500)
                g_f1[(m0 + ty * 4 + i) * 500 + n] = fmaxf(acc[i][j] + bias[n], 0.f);
        }
}

// ---------------- fc2: [f1 | y] @ W2^T + b2, one warp per (b,o) ----------------
__global__ __launch_bounds__(256) void fc2_k(
    const float* __restrict__ y, const float* __restrict__ w2,
    const float* __restrict__ b2, float* __restrict__ out) {
    int warp = (blockIdx.x * blockDim.x + threadIdx.x) >> 5;
    int lane = threadIdx.x & 31;
    int b = warp >> 1, o = warp & 1;
    const float* f1 = g_f1 + b * 500;
    const float* w = w2 + o * 502;
    float s = 0.f;
    for (int j = lane; j < 500; j += 32) s = fmaf(f1[j], w[j], s);
    if (lane == 0) s += w[500] * y[b * 2] + w[501] * y[b * 2 + 1] + b2[o];
#pragma unroll
    for (int off = 16; off; off >>= 1) s += __shfl_xor_sync(0xffffffffu, s, off);
    if (lane == 0) out[b * 2 + o] = s;
}

// ---------------- launch ----------------
extern "C" void kernel_launch(void* const* d_in, const int* in_sizes, int n_in,
                              void* d_out, int out_size) {
    const float* x   = (const float*)d_in[0];
    const float* y   = (const float*)d_in[1];
    const float* c1w = (const float*)d_in[2];
    const float* c1b = (const float*)d_in[3];
    const float* c2w = (const float*)d_in[4];
    const float* c2b = (const float*)d_in[5];
    const float* pw  = (const float*)d_in[6];
    const float* pb  = (const float*)d_in[7];
    const float* rw  = (const float*)d_in[8];
    const float* f1w = (const float*)d_in[9];
    const float* f1b = (const float*)d_in[10];
    const float* f2w = (const float*)d_in[11];
    const float* f2b = (const float*)d_in[12];
    float* out = (float*)d_out;

    const int conv2_smem = (8960 + 52 * 288) * 4;   // 95744 B
    const int pcaps_smem = 16000 * 4;               // 64000 B
    cudaFuncSetAttribute(conv2_pool_k, cudaFuncAttributeMaxDynamicSharedMemorySize, conv2_smem);
    cudaFuncSetAttribute(pcaps_k,      cudaFuncAttributeMaxDynamicSharedMemorySize, pcaps_smem);

    prep_k<<<(26000 + 255) / 256, 256>>>(c2w, pw);
    conv1_pool_k<<<NB, 256>>>(x, c1w, c1b);
    conv2_pool_k<<<NB, 256, conv2_smem>>>(c2b);
    pcaps_k<<<NB / 2, 192, pcaps_smem>>>(pb);
    routing_k<<<(NB * 2) / 8, 256>>>(rw);
    dim3 g4(8, 32);
    fc1_k<<<g4, 256>>>(f1w, f1b);
    fc2_k<<<NB * 2 / 8, 256>>>(y, f2w, f2b, out);
}

// round 2
// speedup vs baseline: 1.4859x; 1.4859x over previous
#include <cuda_runtime.h>
#include <math.h>
#include <stdint.h>

#define NB 2048

// ---------------- scratch (device globals; no allocation) ----------------
__device__ float g_h1[NB * 8960];           // conv1+pool out  [b][20][16][28]
__device__ float g_h2[NB * 3600];           // conv2+pool out  [b][50][6][12]
__device__ float g_p [NB * 1152];           // pcaps conv out  [b][16][72]
__device__ float g_c [NB * 2];              // routed capsule outputs
__device__ float g_f1[NB * 500];            // fc1 relu out
__device__ uint2 g_w2f[64 * 4 * 64];        // conv2 B fragments (tf32 pairs {k,k+4})
__device__ uint4 g_wpa[160 * 32];           // pcaps A fragments (tf32, per-lane a0..a3)
__device__ int2  g_koffc[256];              // conv2 im2col offsets {k,k+4}
__device__ int2  g_koffp[640];              // pcaps im2col offsets {k,k+4}

// ---------------- tf32 helpers ----------------
__device__ __forceinline__ unsigned f2tf(float f) {
    unsigned u; asm("cvt.rna.tf32.f32 %0, %1;" : "=r"(u) : "f"(f)); return u;
}
__device__ __forceinline__ void mma8(float* d, unsigned a0, unsigned a1, unsigned a2,
                                     unsigned a3, unsigned b0, unsigned b1) {
    asm volatile(
        "mma.sync.aligned.m16n8k8.row.col.f32.tf32.tf32.f32 "
        "{%0,%1,%2,%3},{%4,%5,%6,%7},{%8,%9},{%0,%1,%2,%3};"
        : "+f"(d[0]), "+f"(d[1]), "+f"(d[2]), "+f"(d[3])
        : "r"(a0), "r"(a1), "r"(a2), "r"(a3), "r"(b0), "r"(b1));
}

// ---------------- prep: weight fragment layouts + im2col offset tables ----------------
__global__ void prep_k(const float* __restrict__ w2, const float* __restrict__ pw) {
    int i = blockIdx.x * blockDim.x + threadIdx.x;
    if (i < 16384) {  // conv2 B frags: [kchunk 64][kk 4][n 64] pairs {k, k+4}
        int kc = i >> 8, rem = i & 255, kk = rem >> 6, n = rem & 63;
        int k = kc * 8 + kk;
        float v0 = (n < 50 && k     < 500) ? w2[n * 500 + k]     : 0.f;
        float v1 = (n < 50 && k + 4 < 500) ? w2[n * 500 + k + 4] : 0.f;
        g_w2f[i] = make_uint2(f2tf(v0), f2tf(v1));
    }
    if (i < 5120) {   // pcaps A frags: [kchunk 160][lane 32] -> {a0,a1,a2,a3}
        int kc = i >> 5, lane = i & 31, g = lane >> 2, t = lane & 3;
        int k0 = kc * 8;
        float v0 = (k0 + t     < 1250) ? pw[g * 1250 + k0 + t]           : 0.f;
        float v1 = (k0 + t     < 1250) ? pw[(g + 8) * 1250 + k0 + t]     : 0.f;
        float v2 = (k0 + t + 4 < 1250) ? pw[g * 1250 + k0 + t + 4]       : 0.f;
        float v3 = (k0 + t + 4 < 1250) ? pw[(g + 8) * 1250 + k0 + t + 4] : 0.f;
        g_wpa[i] = make_uint4(f2tf(v0), f2tf(v1), f2tf(v2), f2tf(v3));
    }
    if (i < 256) {    // conv2 offsets: layout [20][16][28], zero slot 8960
        int k = (i >> 2) * 8 + (i & 3);
        int o0 = (k < 500) ? (k / 25) * 448 + ((k % 25) / 5) * 28 + (k % 5) : 8960;
        int k4 = k + 4;
        int o1 = (k4 < 500) ? (k4 / 25) * 448 + ((k4 % 25) / 5) * 28 + (k4 % 5) : 8960;
        g_koffc[i] = make_int2(o0, o1);
    }
    if (i < 640) {    // pcaps offsets: padded layout [50][10][16], zero slot 8000
        int k = (i >> 2) * 8 + (i & 3);
        int o0 = (k < 1250) ? (k / 25) * 160 + ((k % 25) / 5) * 16 + (k % 5) : 8000;
        int k4 = k + 4;
        int o1 = (k4 < 1250) ? (k4 / 25) * 160 + ((k4 % 25) / 5) * 16 + (k4 % 5) : 8000;
        g_koffp[i] = make_int2(o0, o1);
    }
}

// ---------------- conv1 (1->20, 5x5 valid) + 2x2 maxpool (exact fp32 SIMT) ----------------
__global__ __launch_bounds__(256) void conv1_pool_k(
    const float* __restrict__ x, const float* __restrict__ w, const float* __restrict__ bias) {
    __shared__ __align__(16) float sx[36 * 60];
    __shared__ float sw[500];
    __shared__ float sb[20];
    int b = blockIdx.x;
    for (int i = threadIdx.x; i < 2160; i += 256) sx[i] = x[b * 2160 + i];
    for (int i = threadIdx.x; i < 500;  i += 256) sw[i] = w[i];
    if (threadIdx.x < 20) sb[threadIdx.x] = bias[threadIdx.x];
    __syncthreads();
    for (int i = threadIdx.x; i < 8960; i += 256) {
        int oc = i / 448, rem = i % 448, ph = rem / 28, pw = rem % 28;
        int r0 = ph * 2, c0 = pw * 2;
        float patch[6][6];
#pragma unroll
        for (int pr = 0; pr < 6; pr++) {
            const float2* row = (const float2*)&sx[(r0 + pr) * 60 + c0];
            float2 p0 = row[0], p1 = row[1], p2 = row[2];
            patch[pr][0] = p0.x; patch[pr][1] = p0.y;
            patch[pr][2] = p1.x; patch[pr][3] = p1.y;
            patch[pr][4] = p2.x; patch[pr][5] = p2.y;
        }
        const float* wp = &sw[oc * 25];
        float a00 = 0, a01 = 0, a10 = 0, a11 = 0;
#pragma unroll
        for (int kr = 0; kr < 5; kr++)
#pragma unroll
            for (int kc = 0; kc < 5; kc++) {
                float wv = wp[kr * 5 + kc];
                a00 = fmaf(patch[kr][kc],         wv, a00);
                a01 = fmaf(patch[kr][kc + 1],     wv, a01);
                a10 = fmaf(patch[kr + 1][kc],     wv, a10);
                a11 = fmaf(patch[kr + 1][kc + 1], wv, a11);
            }
        g_h1[b * 8960 + i] = fmaxf(fmaxf(a00, a01), fmaxf(a10, a11)) + sb[oc];
    }
}

// ---------------- conv2 via tf32 mma: per image, M=288, N=64, K=512 ----------------
// 288 threads = 9 warps, each warp owns 2 m16-strips x 8 n-tiles.
// smem: sxt[9292] u32 tf32 (zero-padded slot region) | koff int2[256] | Bf uint2 (stride 65)
__global__ __launch_bounds__(288) void conv2_mma_k(const float* __restrict__ bias) {
    extern __shared__ __align__(16) unsigned char cs[];
    unsigned* sxt   = (unsigned*)cs;                   // 9292 u32
    int2*     skoff = (int2*)(cs + 37168);             // 256 int2
    uint2*    sBf   = (uint2*)(cs + 37168 + 2048);     // up to idx 4158
    float*    sconv = (float*)cs;                      // phase-2 alias: 50*288 floats

    int b = blockIdx.x, tid = threadIdx.x;
    int warp = tid >> 5, lane = tid & 31, g = lane >> 2, t = lane & 3;

    for (int i = tid; i < 8960; i += 288) sxt[i] = f2tf(g_h1[b * 8960 + i]);
    for (int i = 8960 + tid; i < 9292; i += 288) sxt[i] = 0u;   // zero-slot region
    for (int i = tid; i < 256; i += 288) skoff[i] = g_koffc[i];

    float acc[2][8][4];
#pragma unroll
    for (int s = 0; s < 2; s++)
#pragma unroll
        for (int nt = 0; nt < 8; nt++)
#pragma unroll
            for (int q = 0; q < 4; q++) acc[s][nt][q] = 0.f;

    int pb[2][2];
#pragma unroll
    for (int s = 0; s < 2; s++) {
        int m0 = (warp * 2 + s) * 16 + g;
        pb[s][0] = (m0 / 24) * 28 + (m0 % 24);
        int m1 = m0 + 8;
        pb[s][1] = (m1 / 24) * 28 + (m1 % 24);
    }

    for (int win = 0; win < 4; win++) {
        __syncthreads();
        for (int i = tid; i < 4096; i += 288) {
            int row = i >> 6, n = i & 63;
            sBf[row * 65 + n] = g_w2f[win * 4096 + i];
        }
        __syncthreads();
#pragma unroll 4
        for (int wk = 0; wk < 16; wk++) {
            int2 ko = skoff[(win * 16 + wk) * 4 + t];
            unsigned a[2][4];
#pragma unroll
            for (int s = 0; s < 2; s++) {
                a[s][0] = sxt[pb[s][0] + ko.x];
                a[s][1] = sxt[pb[s][1] + ko.x];
                a[s][2] = sxt[pb[s][0] + ko.y];
                a[s][3] = sxt[pb[s][1] + ko.y];
            }
#pragma unroll
            for (int nt = 0; nt < 8; nt++) {
                uint2 bb = sBf[(wk * 4 + t) * 65 + nt * 8 + g];
                mma8(acc[0][nt], a[0][0], a[0][1], a[0][2], a[0][3], bb.x, bb.y);
                mma8(acc[1][nt], a[1][0], a[1][1], a[1][2], a[1][3], bb.x, bb.y);
            }
        }
    }
    __syncthreads();
    // write conv results pre-pool: sconv[n*288 + m]
#pragma unroll
    for (int s = 0; s < 2; s++) {
        int m0 = (warp * 2 + s) * 16 + g;
#pragma unroll
        for (int nt = 0; nt < 8; nt++) {
            int n0 = nt * 8 + 2 * t;
            if (n0 < 50) {
                sconv[n0 * 288 + m0]     = acc[s][nt][0];
                sconv[n0 * 288 + m0 + 8] = acc[s][nt][2];
            }
            if (n0 + 1 < 50) {
                sconv[(n0 + 1) * 288 + m0]     = acc[s][nt][1];
                sconv[(n0 + 1) * 288 + m0 + 8] = acc[s][nt][3];
            }
        }
    }
    __syncthreads();
    for (int i = tid; i < 3600; i += 288) {
        int oc = i / 72, rem = i % 72, ph = rem / 12, pw = rem % 12;
        const float* base = &sconv[oc * 288 + ph * 48 + pw * 2];
        float m = fmaxf(fmaxf(base[0], base[1]), fmaxf(base[24], base[25]));
        g_h2[b * 3600 + i] = m + bias[oc];
    }
}

// ---------------- pcaps via tf32 mma: per image, M=16(oc), N=72(pos), K=1280 ----------------
// 288 threads = 9 warps, warp w -> n-tile w (n = w*8..w*8+7)
__global__ __launch_bounds__(288) void pcaps_mma_k(const float* __restrict__ bias) {
    __shared__ unsigned sh2p[8096];   // padded [50][10][16] tf32 + zero slot at 8000+
    __shared__ int2 skp[640];
    int b = blockIdx.x, tid = threadIdx.x;
    int warp = tid >> 5, lane = tid & 31, g = lane >> 2, t = lane & 3;

    for (int i = tid; i < 8096; i += 288) sh2p[i] = 0u;
    for (int i = tid; i < 640; i += 288) skp[i] = g_koffp[i];
    __syncthreads();
    for (int i = tid; i < 3600; i += 288) {
        int ic = i / 72, rem = i % 72, r = rem / 12, c = rem % 12;
        sh2p[ic * 160 + (r + 2) * 16 + (c + 2)] = f2tf(g_h2[b * 3600 + i]);
    }
    __syncthreads();

    int nt = warp;                       // 0..8
    int p = nt * 8 + g;                  // B col position for b0/b1
    int pbase = (p / 12) * 16 + (p % 12);
    float acc[4] = {0.f, 0.f, 0.f, 0.f};
    for (int kc = 0; kc < 160; kc++) {
        uint4 aa = g_wpa[kc * 32 + lane];
        int2 ko = skp[kc * 4 + t];
        unsigned b0 = sh2p[ko.x + pbase];
        unsigned b1 = sh2p[ko.y + pbase];
        mma8(acc, aa.x, aa.y, aa.z, aa.w, b0, b1);
    }
    // D[m=oc][n=pos]: rows g, g+8; cols nt*8 + 2t, +1
    int oc0 = g;
    int n0 = nt * 8 + 2 * t;
    float bsA = bias[oc0], bsB = bias[oc0 + 8];
    float* po = &g_p[b * 1152];
    po[oc0 * 72 + n0]           = acc[0] + bsA;
    po[oc0 * 72 + n0 + 1]       = acc[1] + bsA;
    po[(oc0 + 8) * 72 + n0]     = acc[2] + bsB;
    po[(oc0 + 8) * 72 + n0 + 1] = acc[3] + bsB;
}

// ---------------- squash + priors + 3-iter dynamic routing (unchanged) ----------------
__device__ __forceinline__ float sq1(float s) { return s * fabsf(s) / (1.f + s * s); }

__global__ __launch_bounds__(256) void routing_k(const float* __restrict__ rw) {
    int warp = (blockIdx.x * blockDim.x + threadIdx.x) >> 5;
    int lane = threadIdx.x & 31;
    int b = warp >> 1, k = warp & 1;
    float pr[9];
#pragma unroll
    for (int j = 0; j < 9; j++) {
        int r = lane + 32 * j;
        int cw = r / 72, hw = r % 72;
        const float* pb = g_p + b * 1152 + cw * 72 + hw;
        float u0 = pb[0], u1 = pb[288], u2 = pb[576], u3 = pb[864];
        float n2 = u0 * u0 + u1 * u1 + u2 * u2 + u3 * u3;
        float f = sqrtf(n2) / (1.f + n2);
        float4 w4 = *(const float4*)&rw[(k * 288 + r) * 4];
        pr[j] = f * (u0 * w4.x + u1 * w4.y + u2 * w4.z + u3 * w4.w);
    }
    float S = 0.f;
#pragma unroll
    for (int j = 0; j < 9; j++) S += pr[j];
#pragma unroll
    for (int o = 16; o; o >>= 1) S += __shfl_xor_sync(0xffffffffu, S, o);
    float s = S * (1.f / 288.f);
    float v = sq1(s);
    float vsum = v;
#pragma unroll
    for (int it = 0; it < 2; it++) {
        float m = -1e30f;
#pragma unroll
        for (int j = 0; j < 9; j++) m = fmaxf(m, pr[j] * vsum);
#pragma unroll
        for (int o = 16; o; o >>= 1) m = fmaxf(m, __shfl_xor_sync(0xffffffffu, m, o));
        float Z = 0.f, T = 0.f;
#pragma unroll
        for (int j = 0; j < 9; j++) {
            float e = __expf(pr[j] * vsum - m);
            Z += e;
            T = fmaf(e, pr[j], T);
        }
#pragma unroll
        for (int o = 16; o; o >>= 1) {
            Z += __shfl_xor_sync(0xffffffffu, Z, o);
            T += __shfl_xor_sync(0xffffffffu, T, o);
        }
        float s2 = T / Z;
        v = sq1(s2);
        vsum += v;
    }
    if (lane == 0) g_c[b * 2 + k] = v;
}

// ---------------- fc1 via tf32 mma: M=2048, N=512(500), K=3616(3602) ----------------
// CTA tile 128x64, 256 threads = 8 warps (warp = m16 strip), k-tile 32
__global__ __launch_bounds__(256) void fc1_mma_k(const float* __restrict__ W,
                                                 const float* __restrict__ bias) {
    __shared__ unsigned As[32 * 136];          // [k][m] swizzled (stride 136)
    __shared__ uint2 Bsp[16 * 65 + 64];        // [(kc*4+kk)*65 + n] pairs {k,k+4}
    int m0 = blockIdx.y * 128, n0 = blockIdx.x * 64;
    int tid = threadIdx.x, warp = tid >> 5, lane = tid & 31, g = lane >> 2, t = lane & 3;
    int mA = tid & 127, ksl = (tid >> 7) * 16;
    int nB = tid & 63,  kg  = tid >> 6;

    float acc[8][4];
#pragma unroll
    for (int nt = 0; nt < 8; nt++)
#pragma unroll
        for (int q = 0; q < 4; q++) acc[nt][q] = 0.f;

    for (int kt = 0; kt < 113; kt++) {
        int k0 = kt * 32;
        // --- load A tile (128m x 32k), tf32 convert ---
        if (k0 + 32 <= 3600) {
            const float* src = &g_h2[(m0 + mA) * 3600 + k0 + ksl];
#pragma unroll
            for (int q = 0; q < 4; q++) {
                float4 v = *(const float4*)(src + q * 4);
                As[(ksl + q * 4 + 0) * 136 + mA] = f2tf(v.x);
                As[(ksl + q * 4 + 1) * 136 + mA] = f2tf(v.y);
                As[(ksl + q * 4 + 2) * 136 + mA] = f2tf(v.z);
                As[(ksl + q * 4 + 3) * 136 + mA] = f2tf(v.w);
            }
        } else {
#pragma unroll
            for (int q = 0; q < 16; q++) {
                int k = k0 + ksl + q;
                float v = 0.f;
                if (k < 3600) v = g_h2[(m0 + mA) * 3600 + k];
                else if (k < 3602) v = g_c[(m0 + mA) * 2 + (k - 3600)];
                As[(ksl + q) * 136 + mA] = f2tf(v);
            }
        }
        // --- load B tile (64n x 32k) into pair layout ---
        {
            int n = n0 + nB;
            float v[8];
            if (n < 500 && k0 + 32 <= 3602) {
                const float* wr = &W[n * 3602 + k0 + kg * 8];
#pragma unroll
                for (int jj = 0; jj < 4; jj++) {
                    float2 pp = *(const float2*)(wr + jj * 2);
                    v[jj * 2] = pp.x; v[jj * 2 + 1] = pp.y;
                }
            } else {
#pragma unroll
                for (int j = 0; j < 8; j++) {
                    int k = k0 + kg * 8 + j;
                    v[j] = (n < 500 && k < 3602) ? W[n * 3602 + k] : 0.f;
                }
            }
#pragma unroll
            for (int kk = 0; kk < 4; kk++)
                Bsp[(kg * 4 + kk) * 65 + nB] = make_uint2(f2tf(v[kk]), f2tf(v[kk + 4]));
        }
        __syncthreads();
#pragma unroll
        for (int kc = 0; kc < 4; kc++) {
            unsigned a0 = As[(kc * 8 + t) * 136 + warp * 16 + g];
            unsigned a1 = As[(kc * 8 + t) * 136 + warp * 16 + g + 8];
            unsigned a2 = As[(kc * 8 + t + 4) * 136 + warp * 16 + g];
            unsigned a3 = As[(kc * 8 + t + 4) * 136 + warp * 16 + g + 8];
#pragma unroll
            for (int nt = 0; nt < 8; nt++) {
                uint2 bb = Bsp[(kc * 4 + t) * 65 + nt * 8 + g];
                mma8(acc[nt], a0, a1, a2, a3, bb.x, bb.y);
            }
        }
        __syncthreads();
    }
    int mrow = m0 + warp * 16 + g;
#pragma unroll
    for (int nt = 0; nt < 8; nt++) {
        int n = n0 + nt * 8 + 2 * t;
        if (n < 500) {
            float bv = bias[n];
            g_f1[mrow * 500 + n]       = fmaxf(acc[nt][0] + bv, 0.f);
            g_f1[(mrow + 8) * 500 + n] = fmaxf(acc[nt][2] + bv, 0.f);
        }
        if (n + 1 < 500) {
            float bv = bias[n + 1];
            g_f1[mrow * 500 + n + 1]       = fmaxf(acc[nt][1] + bv, 0.f);
            g_f1[(mrow + 8) * 500 + n + 1] = fmaxf(acc[nt][3] + bv, 0.f);
        }
    }
}

// ---------------- fc2: [f1 | y] @ W2^T + b2, one warp per (b,o) ----------------
__global__ __launch_bounds__(256) void fc2_k(
    const float* __restrict__ y, const float* __restrict__ w2,
    const float* __restrict__ b2, float* __restrict__ out) {
    int warp = (blockIdx.x * blockDim.x + threadIdx.x) >> 5;
    int lane = threadIdx.x & 31;
    int b = warp >> 1, o = warp & 1;
    const float* f1 = g_f1 + b * 500;
    const float* w = w2 + o * 502;
    float s = 0.f;
    for (int j = lane; j < 500; j += 32) s = fmaf(f1[j], w[j], s);
    if (lane == 0) s += w[500] * y[b * 2] + w[501] * y[b * 2 + 1] + b2[o];
#pragma unroll
    for (int off = 16; off; off >>= 1) s += __shfl_xor_sync(0xffffffffu, s, off);
    if (lane == 0) out[b * 2 + o] = s;
}

// ---------------- launch ----------------
extern "C" void kernel_launch(void* const* d_in, const int* in_sizes, int n_in,
                              void* d_out, int out_size) {
    const float* x   = (const float*)d_in[0];
    const float* y   = (const float*)d_in[1];
    const float* c1w = (const float*)d_in[2];
    const float* c1b = (const float*)d_in[3];
    const float* c2w = (const float*)d_in[4];
    const float* c2b = (const float*)d_in[5];
    const float* pw  = (const float*)d_in[6];
    const float* pb  = (const float*)d_in[7];
    const float* rw  = (const float*)d_in[8];
    const float* f1w = (const float*)d_in[9];
    const float* f1b = (const float*)d_in[10];
    const float* f2w = (const float*)d_in[11];
    const float* f2b = (const float*)d_in[12];
    float* out = (float*)d_out;

    const int conv2_smem = 37168 + 2048 + 4159 * 8;   // 72488 B
    cudaFuncSetAttribute(conv2_mma_k, cudaFuncAttributeMaxDynamicSharedMemorySize, conv2_smem);

    prep_k<<<64, 256>>>(c2w, pw);
    conv1_pool_k<<<NB, 256>>>(x, c1w, c1b);
    conv2_mma_k<<<NB, 288, conv2_smem>>>(c2b);
    pcaps_mma_k<<<NB, 288>>>(pb);
    routing_k<<<(NB * 2) / 8, 256>>>(rw);
    dim3 g4(8, 16);
    fc1_mma_k<<<g4, 256>>>(f1w, f1b);
    fc2_k<<<NB * 2 / 8, 256>>>(y, f2w, f2b, out);
}

// round 3
// speedup vs baseline: 1.5595x; 1.0496x over previous
#include <cuda_runtime.h>
#include <math.h>
#include <stdint.h>

#define NB 2048

// ---------------- scratch (device globals; no allocation) ----------------
__device__ float g_h2[NB * 3600];           // conv2+pool out (tf32-rounded) [b][50][6][12]
__device__ float g_c [NB * 2];              // routed capsule outputs
__device__ float g_f1[NB * 500];            // fc1 relu out
__device__ uint2 g_w2f[64 * 4 * 64];        // conv2 B frags: [kc][kk][n] tf32 pairs {k,k+4}
__device__ uint4 g_wpa[160 * 32];           // pcaps A frags (tf32, per-lane a0..a3)
__device__ uint2 g_w1p[452 * 4 * 512];      // fc1 B frags: [kc][kk][n] tf32 pairs {k,k+4}
__device__ int2  g_koffc[256];              // conv2 im2col offsets {k,k+4}
__device__ int2  g_koffp[640];              // pcaps im2col offsets {k,k+4}

// ---------------- tf32 helpers ----------------
__device__ __forceinline__ unsigned f2tf(float f) {
    unsigned u; asm("cvt.rna.tf32.f32 %0, %1;" : "=r"(u) : "f"(f)); return u;
}
__device__ __forceinline__ void mma8(float* d, unsigned a0, unsigned a1, unsigned a2,
                                     unsigned a3, unsigned b0, unsigned b1) {
    asm volatile(
        "mma.sync.aligned.m16n8k8.row.col.f32.tf32.tf32.f32 "
        "{%0,%1,%2,%3},{%4,%5,%6,%7},{%8,%9},{%0,%1,%2,%3};"
        : "+f"(d[0]), "+f"(d[1]), "+f"(d[2]), "+f"(d[3])
        : "r"(a0), "r"(a1), "r"(a2), "r"(a3), "r"(b0), "r"(b1));
}

// ---------------- prep: weight fragment layouts + im2col offset tables ----------------
__global__ void prep_k(const float* __restrict__ w2, const float* __restrict__ pw,
                       const float* __restrict__ w1) {
    int gtid = blockIdx.x * blockDim.x + threadIdx.x;
    int stride = gridDim.x * blockDim.x;
    for (int i = gtid; i < 16384; i += stride) {   // conv2 B frags
        int kc = i >> 8, rem = i & 255, kk = rem >> 6, n = rem & 63;
        int k = kc * 8 + kk;
        float v0 = (n < 50 && k     < 500) ? w2[n * 500 + k]     : 0.f;
        float v1 = (n < 50 && k + 4 < 500) ? w2[n * 500 + k + 4] : 0.f;
        g_w2f[i] = make_uint2(f2tf(v0), f2tf(v1));
    }
    for (int i = gtid; i < 5120; i += stride) {    // pcaps A frags
        int kc = i >> 5, lane = i & 31, g = lane >> 2, t = lane & 3;
        int k0 = kc * 8;
        float v0 = (k0 + t     < 1250) ? pw[g * 1250 + k0 + t]           : 0.f;
        float v1 = (k0 + t     < 1250) ? pw[(g + 8) * 1250 + k0 + t]     : 0.f;
        float v2 = (k0 + t + 4 < 1250) ? pw[g * 1250 + k0 + t + 4]       : 0.f;
        float v3 = (k0 + t + 4 < 1250) ? pw[(g + 8) * 1250 + k0 + t + 4] : 0.f;
        g_wpa[i] = make_uint4(f2tf(v0), f2tf(v1), f2tf(v2), f2tf(v3));
    }
    for (int i = gtid; i < 256; i += stride) {     // conv2 offsets
        int k = (i >> 2) * 8 + (i & 3);
        int o0 = (k < 500) ? (k / 25) * 448 + ((k % 25) / 5) * 28 + (k % 5) : 8960;
        int k4 = k + 4;
        int o1 = (k4 < 500) ? (k4 / 25) * 448 + ((k4 % 25) / 5) * 28 + (k4 % 5) : 8960;
        g_koffc[i] = make_int2(o0, o1);
    }
    for (int i = gtid; i < 640; i += stride) {     // pcaps offsets
        int k = (i >> 2) * 8 + (i & 3);
        int o0 = (k < 1250) ? (k / 25) * 160 + ((k % 25) / 5) * 16 + (k % 5) : 8000;
        int k4 = k + 4;
        int o1 = (k4 < 1250) ? (k4 / 25) * 160 + ((k4 % 25) / 5) * 16 + (k4 % 5) : 8000;
        g_koffp[i] = make_int2(o0, o1);
    }
    for (int i = gtid; i < 452 * 4 * 512; i += stride) {  // fc1 B frags
        int kc = i >> 11, rem = i & 2047, kk = rem >> 9, n = rem & 511;
        int k = kc * 8 + kk;
        float v0 = (n < 500 && k     < 3602) ? w1[n * 3602 + k]     : 0.f;
        float v1 = (n < 500 && k + 4 < 3602) ? w1[n * 3602 + k + 4] : 0.f;
        g_w1p[i] = make_uint2(f2tf(v0), f2tf(v1));
    }
}

// ================= fused backbone: conv1+pool -> conv2(mma)+pool -> pcaps(mma) -> routing =================
// one CTA per image, 288 threads = 9 warps
// dyn smem layout (phase-aliased):
//   [0      .. 37168)  sxt: conv1 out as tf32 u32 [9292] (phase1 A)  |  phase3 alias: sconv float[14400] (0..57600)
//   [37168  .. 39216)  skoffc int2[256]                               |  phase6 alias: sp float[1152] @ 0
//   [39216  .. 72488)  sBf uint2[4159]
//   [57600  .. 66240)  sx1 float[2160] (phase0 input; dead before sBf win0 load)   <- overlaps sBf tail / sh2p
//   [57600  .. 89984)  sh2p u32[8096] (padded pcaps input)
//   [89984  .. 95104)  skoffp int2[640]
__device__ __forceinline__ float sq1(float s) { return s * fabsf(s) / (1.f + s * s); }

__global__ __launch_bounds__(288, 2) void backbone_k(
    const float* __restrict__ x, const float* __restrict__ c1w, const float* __restrict__ c1b,
    const float* __restrict__ c2b, const float* __restrict__ pcb, const float* __restrict__ rw) {
    extern __shared__ __align__(16) unsigned char cs[];
    unsigned* sxt    = (unsigned*)cs;
    int2*     skoffc = (int2*)(cs + 37168);
    uint2*    sBf    = (uint2*)(cs + 39216);
    float*    sconv  = (float*)cs;
    float*    sp     = (float*)cs;
    float*    sx1    = (float*)(cs + 57600);
    unsigned* sh2p   = (unsigned*)(cs + 57600);
    int2*     skoffp = (int2*)(cs + 89984);
    __shared__ float sw1[500];
    __shared__ float sb1[20];

    int b = blockIdx.x, tid = threadIdx.x;
    int warp = tid >> 5, lane = tid & 31, g = lane >> 2, t = lane & 3;

    // ---- P0: load input, conv1 weights, conv2 offsets ----
    for (int i = tid; i < 2160; i += 288) sx1[i] = x[b * 2160 + i];
    for (int i = tid; i < 500;  i += 288) sw1[i] = c1w[i];
    if (tid < 20) sb1[tid] = c1b[tid];
    for (int i = tid; i < 256; i += 288) skoffc[i] = g_koffc[i];
    __syncthreads();

    // ---- conv1 (1->20, 5x5) + 2x2 maxpool, exact fp32; write tf32 into sxt ----
    for (int i = tid; i < 8960; i += 288) {
        int oc = i / 448, rem = i % 448, ph = rem / 28, pw = rem % 28;
        int r0 = ph * 2, c0 = pw * 2;
        float patch[6][6];
#pragma unroll
        for (int pr = 0; pr < 6; pr++) {
            const float2* row = (const float2*)&sx1[(r0 + pr) * 60 + c0];
            float2 p0 = row[0], p1 = row[1], p2 = row[2];
            patch[pr][0] = p0.x; patch[pr][1] = p0.y;
            patch[pr][2] = p1.x; patch[pr][3] = p1.y;
            patch[pr][4] = p2.x; patch[pr][5] = p2.y;
        }
        const float* wp = &sw1[oc * 25];
        float a00 = 0, a01 = 0, a10 = 0, a11 = 0;
#pragma unroll
        for (int kr = 0; kr < 5; kr++)
#pragma unroll
            for (int kc = 0; kc < 5; kc++) {
                float wv = wp[kr * 5 + kc];
                a00 = fmaf(patch[kr][kc],         wv, a00);
                a01 = fmaf(patch[kr][kc + 1],     wv, a01);
                a10 = fmaf(patch[kr + 1][kc],     wv, a10);
                a11 = fmaf(patch[kr + 1][kc + 1], wv, a11);
            }
        sxt[i] = f2tf(fmaxf(fmaxf(a00, a01), fmaxf(a10, a11)) + sb1[oc]);
    }
    for (int i = 8960 + tid; i < 9292; i += 288) sxt[i] = 0u;
    __syncthreads();

    // ---- conv2 via tf32 mma: M=288, N=56(50), K=512(500) ----
    float acc[2][7][4];
#pragma unroll
    for (int s = 0; s < 2; s++)
#pragma unroll
        for (int nt = 0; nt < 7; nt++)
#pragma unroll
            for (int q = 0; q < 4; q++) acc[s][nt][q] = 0.f;

    int pb[2][2];
#pragma unroll
    for (int s = 0; s < 2; s++) {
        int m0 = (warp * 2 + s) * 16 + g;
        pb[s][0] = (m0 / 24) * 28 + (m0 % 24);
        int m1 = m0 + 8;
        pb[s][1] = (m1 / 24) * 28 + (m1 % 24);
    }

    for (int win = 0; win < 4; win++) {
        for (int i = tid; i < 4096; i += 288) {
            int row = i >> 6, n = i & 63;
            sBf[row * 65 + n] = g_w2f[win * 4096 + i];
        }
        __syncthreads();
#pragma unroll 4
        for (int wk = 0; wk < 16; wk++) {
            int2 ko = skoffc[(win * 16 + wk) * 4 + t];
            unsigned a[2][4];
#pragma unroll
            for (int s = 0; s < 2; s++) {
                a[s][0] = sxt[pb[s][0] + ko.x];
                a[s][1] = sxt[pb[s][1] + ko.x];
                a[s][2] = sxt[pb[s][0] + ko.y];
                a[s][3] = sxt[pb[s][1] + ko.y];
            }
#pragma unroll
            for (int nt = 0; nt < 7; nt++) {
                uint2 bb = sBf[(wk * 4 + t) * 65 + nt * 8 + g];
                mma8(acc[0][nt], a[0][0], a[0][1], a[0][2], a[0][3], bb.x, bb.y);
                mma8(acc[1][nt], a[1][0], a[1][1], a[1][2], a[1][3], bb.x, bb.y);
            }
        }
        __syncthreads();
    }

    // ---- write conv2 results pre-pool: sconv[n*288 + m] (aliases sxt; all mma done) ----
#pragma unroll
    for (int s = 0; s < 2; s++) {
        int m0 = (warp * 2 + s) * 16 + g;
#pragma unroll
        for (int nt = 0; nt < 7; nt++) {
            int n0 = nt * 8 + 2 * t;
            if (n0 < 50) {
                sconv[n0 * 288 + m0]     = acc[s][nt][0];
                sconv[n0 * 288 + m0 + 8] = acc[s][nt][2];
            }
            if (n0 + 1 < 50) {
                sconv[(n0 + 1) * 288 + m0]     = acc[s][nt][1];
                sconv[(n0 + 1) * 288 + m0 + 8] = acc[s][nt][3];
            }
        }
    }
    // zero pcaps padded buffer + load pcaps offsets
    for (int i = tid; i < 8096; i += 288) sh2p[i] = 0u;
    for (int i = tid; i < 640; i += 288) skoffp[i] = g_koffp[i];
    __syncthreads();

    // ---- maxpool + bias -> tf32; write padded smem + g_h2 ----
    for (int i = tid; i < 3600; i += 288) {
        int oc = i / 72, rem = i % 72, ph = rem / 12, pw = rem % 12;
        const float* base = &sconv[oc * 288 + ph * 48 + pw * 2];
        float m = fmaxf(fmaxf(base[0], base[1]), fmaxf(base[24], base[25])) + c2b[oc];
        unsigned r = f2tf(m);
        sh2p[oc * 160 + (ph + 2) * 16 + (pw + 2)] = r;
        g_h2[b * 3600 + i] = __uint_as_float(r);
    }
    __syncthreads();

    // ---- pcaps via tf32 mma: M=16(oc), N=72(pos, 9 warps x n8), K=1280(1250) ----
    {
        int nt = warp;
        int p = nt * 8 + g;
        int pbase = (p / 12) * 16 + (p % 12);
        float pa[4] = {0.f, 0.f, 0.f, 0.f};
        for (int kc = 0; kc < 160; kc++) {
            uint4 aa = g_wpa[kc * 32 + lane];
            int2 ko = skoffp[kc * 4 + t];
            unsigned b0 = sh2p[ko.x + pbase];
            unsigned b1 = sh2p[ko.y + pbase];
            mma8(pa, aa.x, aa.y, aa.z, aa.w, b0, b1);
        }
        __syncthreads();   // sconv region dead; sp writes begin
        int oc0 = g;
        int n0 = nt * 8 + 2 * t;
        float bsA = pcb[oc0], bsB = pcb[oc0 + 8];
        sp[oc0 * 72 + n0]           = pa[0] + bsA;
        sp[oc0 * 72 + n0 + 1]       = pa[1] + bsA;
        sp[(oc0 + 8) * 72 + n0]     = pa[2] + bsB;
        sp[(oc0 + 8) * 72 + n0 + 1] = pa[3] + bsB;
    }
    __syncthreads();

    // ---- squash + priors + 3-iter routing: warps 0,1 (k = warp) ----
    if (warp < 2) {
        int k = warp;
        float pr[9];
#pragma unroll
        for (int j = 0; j < 9; j++) {
            int r = lane + 32 * j;
            int cw = r / 72, hw = r % 72;
            const float* pbp = sp + cw * 72 + hw;
            float u0 = pbp[0], u1 = pbp[288], u2 = pbp[576], u3 = pbp[864];
            float n2 = u0 * u0 + u1 * u1 + u2 * u2 + u3 * u3;
            float f = sqrtf(n2) / (1.f + n2);
            float4 w4 = *(const float4*)&rw[(k * 288 + r) * 4];
            pr[j] = f * (u0 * w4.x + u1 * w4.y + u2 * w4.z + u3 * w4.w);
        }
        float S = 0.f;
#pragma unroll
        for (int j = 0; j < 9; j++) S += pr[j];
#pragma unroll
        for (int o = 16; o; o >>= 1) S += __shfl_xor_sync(0xffffffffu, S, o);
        float s = S * (1.f / 288.f);
        float v = sq1(s);
        float vsum = v;
#pragma unroll
        for (int it = 0; it < 2; it++) {
            float m = -1e30f;
#pragma unroll
            for (int j = 0; j < 9; j++) m = fmaxf(m, pr[j] * vsum);
#pragma unroll
            for (int o = 16; o; o >>= 1) m = fmaxf(m, __shfl_xor_sync(0xffffffffu, m, o));
            float Z = 0.f, T = 0.f;
#pragma unroll
            for (int j = 0; j < 9; j++) {
                float e = __expf(pr[j] * vsum - m);
                Z += e;
                T = fmaf(e, pr[j], T);
            }
#pragma unroll
            for (int o = 16; o; o >>= 1) {
                Z += __shfl_xor_sync(0xffffffffu, Z, o);
                T += __shfl_xor_sync(0xffffffffu, T, o);
            }
            float s2 = T / Z;
            v = sq1(s2);
            vsum += v;
        }
        if (lane == 0) g_c[b * 2 + k] = v;
    }
}

// ---------------- fc1 via tf32 mma: M=2048, N=512(500), K=3616(3602) ----------------
__global__ __launch_bounds__(256) void fc1_mma_k(const float* __restrict__ bias) {
    __shared__ unsigned As[32 * 136];
    __shared__ uint2 Bsp[16 * 65 + 64];
    int m0 = blockIdx.y * 128, n0 = blockIdx.x * 64;
    int tid = threadIdx.x, warp = tid >> 5, lane = tid & 31, g = lane >> 2, t = lane & 3;
    int mA = tid & 127, ksl = (tid >> 7) * 16;
    int nB = tid & 63,  kg  = tid >> 6;

    float acc[8][4];
#pragma unroll
    for (int nt = 0; nt < 8; nt++)
#pragma unroll
        for (int q = 0; q < 4; q++) acc[nt][q] = 0.f;

    for (int kt = 0; kt < 113; kt++) {
        int k0 = kt * 32;
        // A tile: g_h2 is pre-rounded tf32 -> reinterpret
        if (k0 + 32 <= 3600) {
            const float* src = &g_h2[(m0 + mA) * 3600 + k0 + ksl];
#pragma unroll
            for (int q = 0; q < 4; q++) {
                float4 v = *(const float4*)(src + q * 4);
                As[(ksl + q * 4 + 0) * 136 + mA] = __float_as_uint(v.x);
                As[(ksl + q * 4 + 1) * 136 + mA] = __float_as_uint(v.y);
                As[(ksl + q * 4 + 2) * 136 + mA] = __float_as_uint(v.z);
                As[(ksl + q * 4 + 3) * 136 + mA] = __float_as_uint(v.w);
            }
        } else {
#pragma unroll
            for (int q = 0; q < 16; q++) {
                int k = k0 + ksl + q;
                unsigned v = 0u;
                if (k < 3600) v = __float_as_uint(g_h2[(m0 + mA) * 3600 + k]);
                else if (k < 3602) v = f2tf(g_c[(m0 + mA) * 2 + (k - 3600)]);
                As[(ksl + q) * 136 + mA] = v;
            }
        }
        // B tile from pre-built frags (branch-free)
#pragma unroll
        for (int kk = 0; kk < 4; kk++)
            Bsp[(kg * 4 + kk) * 65 + nB] =
                g_w1p[(((kt * 4 + kg) * 4) + kk) * 512 + n0 + nB];
        __syncthreads();
#pragma unroll
        for (int kc = 0; kc < 4; kc++) {
            unsigned a0 = As[(kc * 8 + t) * 136 + warp * 16 + g];
            unsigned a1 = As[(kc * 8 + t) * 136 + warp * 16 + g + 8];
            unsigned a2 = As[(kc * 8 + t + 4) * 136 + warp * 16 + g];
            unsigned a3 = As[(kc * 8 + t + 4) * 136 + warp * 16 + g + 8];
#pragma unroll
            for (int nt = 0; nt < 8; nt++) {
                uint2 bb = Bsp[(kc * 4 + t) * 65 + nt * 8 + g];
                mma8(acc[nt], a0, a1, a2, a3, bb.x, bb.y);
            }
        }
        __syncthreads();
    }
    int mrow = m0 + warp * 16 + g;
#pragma unroll
    for (int nt = 0; nt < 8; nt++) {
        int n = n0 + nt * 8 + 2 * t;
        if (n < 500) {
            float bv = bias[n];
            g_f1[mrow * 500 + n]       = fmaxf(acc[nt][0] + bv, 0.f);
            g_f1[(mrow + 8) * 500 + n] = fmaxf(acc[nt][2] + bv, 0.f);
        }
        if (n + 1 < 500) {
            float bv = bias[n + 1];
            g_f1[mrow * 500 + n + 1]       = fmaxf(acc[nt][1] + bv, 0.f);
            g_f1[(mrow + 8) * 500 + n + 1] = fmaxf(acc[nt][3] + bv, 0.f);
        }
    }
}

// ---------------- fc2: [f1 | y] @ W2^T + b2, one warp per (b,o) ----------------
__global__ __launch_bounds__(256) void fc2_k(
    const float* __restrict__ y, const float* __restrict__ w2,
    const float* __restrict__ b2, float* __restrict__ out) {
    int warp = (blockIdx.x * blockDim.x + threadIdx.x) >> 5;
    int lane = threadIdx.x & 31;
    int b = warp >> 1, o = warp & 1;
    const float* f1 = g_f1 + b * 500;
    const float* w = w2 + o * 502;
    float s = 0.f;
    for (int j = lane; j < 500; j += 32) s = fmaf(f1[j], w[j], s);
    if (lane == 0) s += w[500] * y[b * 2] + w[501] * y[b * 2 + 1] + b2[o];
#pragma unroll
    for (int off = 16; off; off >>= 1) s += __shfl_xor_sync(0xffffffffu, s, off);
    if (lane == 0) out[b * 2 + o] = s;
}

// ---------------- launch ----------------
extern "C" void kernel_launch(void* const* d_in, const int* in_sizes, int n_in,
                              void* d_out, int out_size) {
    const float* x   = (const float*)d_in[0];
    const float* y   = (const float*)d_in[1];
    const float* c1w = (const float*)d_in[2];
    const float* c1b = (const float*)d_in[3];
    const float* c2w = (const float*)d_in[4];
    const float* c2b = (const float*)d_in[5];
    const float* pw  = (const float*)d_in[6];
    const float* pb  = (const float*)d_in[7];
    const float* rw  = (const float*)d_in[8];
    const float* f1w = (const float*)d_in[9];
    const float* f1b = (const float*)d_in[10];
    const float* f2w = (const float*)d_in[11];
    const float* f2b = (const float*)d_in[12];
    float* out = (float*)d_out;

    const int bb_smem = 95104;
    cudaFuncSetAttribute(backbone_k, cudaFuncAttributeMaxDynamicSharedMemorySize, bb_smem);

    prep_k<<<512, 256>>>(c2w, pw, f1w);
    backbone_k<<<NB, 288, bb_smem>>>(x, c1w, c1b, c2b, pb, rw);
    dim3 g4(8, 16);
    fc1_mma_k<<<g4, 256>>>(f1b);
    fc2_k<<<NB * 2 / 8, 256>>>(y, f2w, f2b, out);
}

// round 4
// speedup vs baseline: 1.6406x; 1.0520x over previous
#include <cuda_runtime.h>
#include <math.h>
#include <stdint.h>

#define NB 2048

// ---------------- scratch (device globals; no allocation) ----------------
__device__ float g_h2[NB * 3600];           // conv2+pool out (tf32-rounded) [b][50][6][12]
__device__ float g_c [NB * 2];              // routed capsule outputs
__device__ float g_f1[NB * 500];            // fc1 relu out
__device__ uint2 g_w2f[64 * 4 * 64];        // conv2 B frags: [kc][kk][n] tf32 pairs {k,k+4}
__device__ uint4 g_wpa[160 * 32];           // pcaps A frags (tf32, per-lane a0..a3)
__device__ uint2 g_w1p[452 * 4 * 512];      // fc1 B frags: [kc][kk][n] tf32 pairs {k,k+4}
__device__ int2  g_koffc[256];              // conv2 im2col offsets {k,k+4}
__device__ int2  g_koffp[640];              // pcaps im2col offsets {k,k+4}

// ---------------- helpers ----------------
__device__ __forceinline__ unsigned f2tf(float f) {
    unsigned u; asm("cvt.rna.tf32.f32 %0, %1;" : "=r"(u) : "f"(f)); return u;
}
__device__ __forceinline__ void mma8(float* d, unsigned a0, unsigned a1, unsigned a2,
                                     unsigned a3, unsigned b0, unsigned b1) {
    asm volatile(
        "mma.sync.aligned.m16n8k8.row.col.f32.tf32.tf32.f32 "
        "{%0,%1,%2,%3},{%4,%5,%6,%7},{%8,%9},{%0,%1,%2,%3};"
        : "+f"(d[0]), "+f"(d[1]), "+f"(d[2]), "+f"(d[3])
        : "r"(a0), "r"(a1), "r"(a2), "r"(a3), "r"(b0), "r"(b1));
}
__device__ __forceinline__ unsigned sptr(const void* p) {
    return (unsigned)__cvta_generic_to_shared(p);
}
#define CP_ASYNC8(dst, src)  asm volatile("cp.async.ca.shared.global [%0], [%1], 8;"  :: "r"(dst), "l"(src))
#define CP_ASYNC16(dst, src) asm volatile("cp.async.cg.shared.global [%0], [%1], 16;" :: "r"(dst), "l"(src))
#define CP_COMMIT            asm volatile("cp.async.commit_group;")
#define CP_WAIT(n)           asm volatile("cp.async.wait_group %0;" :: "n"(n))

// ---------------- prep: weight fragment layouts + im2col offset tables ----------------
__global__ void prep_k(const float* __restrict__ w2, const float* __restrict__ pw,
                       const float* __restrict__ w1) {
    int gtid = blockIdx.x * blockDim.x + threadIdx.x;
    int stride = gridDim.x * blockDim.x;
    for (int i = gtid; i < 16384; i += stride) {   // conv2 B frags
        int kc = i >> 8, rem = i & 255, kk = rem >> 6, n = rem & 63;
        int k = kc * 8 + kk;
        float v0 = (n < 50 && k     < 500) ? w2[n * 500 + k]     : 0.f;
        float v1 = (n < 50 && k + 4 < 500) ? w2[n * 500 + k + 4] : 0.f;
        g_w2f[i] = make_uint2(f2tf(v0), f2tf(v1));
    }
    for (int i = gtid; i < 5120; i += stride) {    // pcaps A frags
        int kc = i >> 5, lane = i & 31, g = lane >> 2, t = lane & 3;
        int k0 = kc * 8;
        float v0 = (k0 + t     < 1250) ? pw[g * 1250 + k0 + t]           : 0.f;
        float v1 = (k0 + t     < 1250) ? pw[(g + 8) * 1250 + k0 + t]     : 0.f;
        float v2 = (k0 + t + 4 < 1250) ? pw[g * 1250 + k0 + t + 4]       : 0.f;
        float v3 = (k0 + t + 4 < 1250) ? pw[(g + 8) * 1250 + k0 + t + 4] : 0.f;
        g_wpa[i] = make_uint4(f2tf(v0), f2tf(v1), f2tf(v2), f2tf(v3));
    }
    for (int i = gtid; i < 256; i += stride) {     // conv2 offsets
        int k = (i >> 2) * 8 + (i & 3);
        int o0 = (k < 500) ? (k / 25) * 448 + ((k % 25) / 5) * 28 + (k % 5) : 8960;
        int k4 = k + 4;
        int o1 = (k4 < 500) ? (k4 / 25) * 448 + ((k4 % 25) / 5) * 28 + (k4 % 5) : 8960;
        g_koffc[i] = make_int2(o0, o1);
    }
    for (int i = gtid; i < 640; i += stride) {     // pcaps offsets
        int k = (i >> 2) * 8 + (i & 3);
        int o0 = (k < 1250) ? (k / 25) * 160 + ((k % 25) / 5) * 16 + (k % 5) : 8000;
        int k4 = k + 4;
        int o1 = (k4 < 1250) ? (k4 / 25) * 160 + ((k4 % 25) / 5) * 16 + (k4 % 5) : 8000;
        g_koffp[i] = make_int2(o0, o1);
    }
    for (int i = gtid; i < 452 * 4 * 512; i += stride) {  // fc1 B frags (K padded to 3616)
        int kc = i >> 11, rem = i & 2047, kk = rem >> 9, n = rem & 511;
        int k = kc * 8 + kk;
        float v0 = (n < 500 && k     < 3602) ? w1[n * 3602 + k]     : 0.f;
        float v1 = (n < 500 && k + 4 < 3602) ? w1[n * 3602 + k + 4] : 0.f;
        g_w1p[i] = make_uint2(f2tf(v0), f2tf(v1));
    }
}

// ================= fused backbone =================
// dyn smem (108864 B), phase-aliased:
//   [0      .. 37168)  sxt u32[9292]         | post-conv2 alias: sconv f32[14400] (..57600) | sp f32[1152]
//   [37184  .. 70464)  sBf0 uint2[4160]
//   [70464  ..103744)  sBf1 uint2[4160]      | phase0 alias: sx1 f32[2160] | post-conv2 alias: sh2p u32[8096]
//   [103744 ..108864)  skoffp int2[640]
__device__ __forceinline__ float sq1(float s) { return s * fabsf(s) / (1.f + s * s); }

__global__ __launch_bounds__(288, 2) void backbone_k(
    const float* __restrict__ x, const float* __restrict__ c1w, const float* __restrict__ c1b,
    const float* __restrict__ c2b, const float* __restrict__ pcb, const float* __restrict__ rw) {
    extern __shared__ __align__(16) unsigned char cs[];
    unsigned* sxt    = (unsigned*)cs;
    uint2*    sBf0   = (uint2*)(cs + 37184);
    uint2*    sBf1   = (uint2*)(cs + 70464);
    float*    sconv  = (float*)cs;
    float*    sp     = (float*)cs;
    float*    sx1    = (float*)(cs + 70464);
    unsigned* sh2p   = (unsigned*)(cs + 70464);
    int2*     skoffp = (int2*)(cs + 103744);
    __shared__ float sw1[500];
    __shared__ float sb1[20];
    __shared__ int2  skoffc[256];

    int b = blockIdx.x, tid = threadIdx.x;
    int warp = tid >> 5, lane = tid & 31, g = lane >> 2, t = lane & 3;

    // ---- P0 ----
    for (int i = tid; i < 2160; i += 288) sx1[i] = x[b * 2160 + i];
    for (int i = tid; i < 500;  i += 288) sw1[i] = c1w[i];
    if (tid < 20) sb1[tid] = c1b[tid];
    for (int i = tid; i < 256; i += 288) skoffc[i] = g_koffc[i];
    for (int i = tid; i < 640; i += 288) skoffp[i] = g_koffp[i];
    __syncthreads();

    // prefetch conv2 B window 0 (hidden behind conv1)
    for (int i = tid; i < 4096; i += 288) {
        int row = i >> 6, n = i & 63;
        CP_ASYNC8(sptr(&sBf0[row * 65 + n]), &g_w2f[i]);
    }
    CP_COMMIT;

    // ---- conv1 + pool (exact fp32) -> tf32 into sxt ----
    for (int i = tid; i < 8960; i += 288) {
        int oc = i / 448, rem = i % 448, ph = rem / 28, pw = rem % 28;
        int r0 = ph * 2, c0 = pw * 2;
        float patch[6][6];
#pragma unroll
        for (int pr = 0; pr < 6; pr++) {
            const float2* row = (const float2*)&sx1[(r0 + pr) * 60 + c0];
            float2 p0 = row[0], p1 = row[1], p2 = row[2];
            patch[pr][0] = p0.x; patch[pr][1] = p0.y;
            patch[pr][2] = p1.x; patch[pr][3] = p1.y;
            patch[pr][4] = p2.x; patch[pr][5] = p2.y;
        }
        const float* wp = &sw1[oc * 25];
        float a00 = 0, a01 = 0, a10 = 0, a11 = 0;
#pragma unroll
        for (int kr = 0; kr < 5; kr++)
#pragma unroll
            for (int kc = 0; kc < 5; kc++) {
                float wv = wp[kr * 5 + kc];
                a00 = fmaf(patch[kr][kc],         wv, a00);
                a01 = fmaf(patch[kr][kc + 1],     wv, a01);
                a10 = fmaf(patch[kr + 1][kc],     wv, a10);
                a11 = fmaf(patch[kr + 1][kc + 1], wv, a11);
            }
        sxt[i] = f2tf(fmaxf(fmaxf(a00, a01), fmaxf(a10, a11)) + sb1[oc]);
    }
    for (int i = 8960 + tid; i < 9292; i += 288) sxt[i] = 0u;
    __syncthreads();   // conv1 done; sx1 dead

    // prefetch window 1 into sBf1 (sx1 region now dead)
    for (int i = tid; i < 4096; i += 288) {
        int row = i >> 6, n = i & 63;
        CP_ASYNC8(sptr(&sBf1[row * 65 + n]), &g_w2f[4096 + i]);
    }
    CP_COMMIT;
    CP_WAIT(1);
    __syncthreads();   // window 0 visible

    // ---- conv2 via tf32 mma: M=288, N=56(50), K=512(500), double-buffered B ----
    float acc[2][7][4];
#pragma unroll
    for (int s = 0; s < 2; s++)
#pragma unroll
        for (int nt = 0; nt < 7; nt++)
#pragma unroll
            for (int q = 0; q < 4; q++) acc[s][nt][q] = 0.f;

    int pb[2][2];
#pragma unroll
    for (int s = 0; s < 2; s++) {
        int m0 = (warp * 2 + s) * 16 + g;
        pb[s][0] = (m0 / 24) * 28 + (m0 % 24);
        int m1 = m0 + 8;
        pb[s][1] = (m1 / 24) * 28 + (m1 % 24);
    }

    for (int win = 0; win < 4; win++) {
        uint2* sBf = (win & 1) ? sBf1 : sBf0;
#pragma unroll 4
        for (int wk = 0; wk < 16; wk++) {
            int2 ko = skoffc[(win * 16 + wk) * 4 + t];
            unsigned a[2][4];
#pragma unroll
            for (int s = 0; s < 2; s++) {
                a[s][0] = sxt[pb[s][0] + ko.x];
                a[s][1] = sxt[pb[s][1] + ko.x];
                a[s][2] = sxt[pb[s][0] + ko.y];
                a[s][3] = sxt[pb[s][1] + ko.y];
            }
#pragma unroll
            for (int nt = 0; nt < 7; nt++) {
                uint2 bb = sBf[(wk * 4 + t) * 65 + nt * 8 + g];
                mma8(acc[0][nt], a[0][0], a[0][1], a[0][2], a[0][3], bb.x, bb.y);
                mma8(acc[1][nt], a[1][0], a[1][1], a[1][2], a[1][3], bb.x, bb.y);
            }
        }
        __syncthreads();   // done reading this buffer
        if (win < 2) {
            for (int i = tid; i < 4096; i += 288) {
                int row = i >> 6, n = i & 63;
                CP_ASYNC8(sptr(&sBf[row * 65 + n]), &g_w2f[(win + 2) * 4096 + i]);
            }
            CP_COMMIT;
            CP_WAIT(1);
        } else {
            CP_WAIT(0);
        }
        __syncthreads();   // next buffer visible
    }

    // ---- writeout conv2 pre-pool (sconv aliases sxt/sBf0) + zero pcaps buffer ----
#pragma unroll
    for (int s = 0; s < 2; s++) {
        int m0 = (warp * 2 + s) * 16 + g;
#pragma unroll
        for (int nt = 0; nt < 7; nt++) {
            int n0 = nt * 8 + 2 * t;
            if (n0 < 50) {
                sconv[n0 * 288 + m0]     = acc[s][nt][0];
                sconv[n0 * 288 + m0 + 8] = acc[s][nt][2];
            }
            if (n0 + 1 < 50) {
                sconv[(n0 + 1) * 288 + m0]     = acc[s][nt][1];
                sconv[(n0 + 1) * 288 + m0 + 8] = acc[s][nt][3];
            }
        }
    }
    for (int i = tid; i < 8096; i += 288) sh2p[i] = 0u;
    __syncthreads();

    // ---- maxpool + bias -> tf32; padded smem + g_h2 ----
    for (int i = tid; i < 3600; i += 288) {
        int oc = i / 72, rem = i % 72, ph = rem / 12, pw = rem % 12;
        const float* base = &sconv[oc * 288 + ph * 48 + pw * 2];
        float m = fmaxf(fmaxf(base[0], base[1]), fmaxf(base[24], base[25])) + c2b[oc];
        unsigned r = f2tf(m);
        sh2p[oc * 160 + (ph + 2) * 16 + (pw + 2)] = r;
        g_h2[b * 3600 + i] = __uint_as_float(r);
    }
    __syncthreads();

    // ---- pcaps via tf32 mma, software-pipelined: M=16, N=72, K=1280 ----
    {
        int nt = warp;
        int p = nt * 8 + g;
        int pbase = (p / 12) * 16 + (p % 12);
        float pa[4] = {0.f, 0.f, 0.f, 0.f};
        uint4 aa = g_wpa[lane];
        int2 ko = skoffp[t];
#pragma unroll 4
        for (int kc = 0; kc < 160; kc++) {
            unsigned b0 = sh2p[ko.x + pbase];
            unsigned b1 = sh2p[ko.y + pbase];
            uint4 aan; int2 kon;
            if (kc < 159) {
                aan = g_wpa[(kc + 1) * 32 + lane];
                kon = skoffp[(kc + 1) * 4 + t];
            }
            mma8(pa, aa.x, aa.y, aa.z, aa.w, b0, b1);
            if (kc < 159) { aa = aan; ko = kon; }
        }
        __syncthreads();   // sconv dead; sp writes begin
        int oc0 = g;
        int n0 = nt * 8 + 2 * t;
        float bsA = pcb[oc0], bsB = pcb[oc0 + 8];
        sp[oc0 * 72 + n0]           = pa[0] + bsA;
        sp[oc0 * 72 + n0 + 1]       = pa[1] + bsA;
        sp[(oc0 + 8) * 72 + n0]     = pa[2] + bsB;
        sp[(oc0 + 8) * 72 + n0 + 1] = pa[3] + bsB;
    }
    __syncthreads();

    // ---- squash + priors + 3-iter routing: warps 0,1 ----
    if (warp < 2) {
        int k = warp;
        float pr[9];
#pragma unroll
        for (int j = 0; j < 9; j++) {
            int r = lane + 32 * j;
            int cw = r / 72, hw = r % 72;
            const float* pbp = sp + cw * 72 + hw;
            float u0 = pbp[0], u1 = pbp[288], u2 = pbp[576], u3 = pbp[864];
            float n2 = u0 * u0 + u1 * u1 + u2 * u2 + u3 * u3;
            float f = sqrtf(n2) / (1.f + n2);
            float4 w4 = *(const float4*)&rw[(k * 288 + r) * 4];
            pr[j] = f * (u0 * w4.x + u1 * w4.y + u2 * w4.z + u3 * w4.w);
        }
        float S = 0.f;
#pragma unroll
        for (int j = 0; j < 9; j++) S += pr[j];
#pragma unroll
        for (int o = 16; o; o >>= 1) S += __shfl_xor_sync(0xffffffffu, S, o);
        float s = S * (1.f / 288.f);
        float v = sq1(s);
        float vsum = v;
#pragma unroll
        for (int it = 0; it < 2; it++) {
            float m = -1e30f;
#pragma unroll
            for (int j = 0; j < 9; j++) m = fmaxf(m, pr[j] * vsum);
#pragma unroll
            for (int o = 16; o; o >>= 1) m = fmaxf(m, __shfl_xor_sync(0xffffffffu, m, o));
            float Z = 0.f, T = 0.f;
#pragma unroll
            for (int j = 0; j < 9; j++) {
                float e = __expf(pr[j] * vsum - m);
                Z += e;
                T = fmaf(e, pr[j], T);
            }
#pragma unroll
            for (int o = 16; o; o >>= 1) {
                Z += __shfl_xor_sync(0xffffffffu, Z, o);
                T += __shfl_xor_sync(0xffffffffu, T, o);
            }
            float s2 = T / Z;
            v = sq1(s2);
            vsum += v;
        }
        if (lane == 0) g_c[b * 2 + k] = v;
    }
}

// ---------------- fc1: M=2048, N=512(500), K=3616(3602); 64x64 tiles, cp.async 2-stage ----------------
__global__ __launch_bounds__(256) void fc1_mma_k(const float* __restrict__ bias) {
    __shared__ __align__(16) unsigned As[2][64 * 36];
    __shared__ __align__(16) uint2 Bsp[2][16 * 65 + 8];
    int m0 = blockIdx.y * 64, n0 = blockIdx.x * 64;
    int tid = threadIdx.x, warp = tid >> 5, lane = tid & 31, g = lane >> 2, t = lane & 3;
    int ws = warp & 3;            // m strip
    int wn = (warp >> 2) * 32;    // n offset
    int mA = tid & 63, kslA = (tid >> 6) * 8;
    int nB = tid & 63, kgB = tid >> 6;

    float acc[4][4];
#pragma unroll
    for (int nt = 0; nt < 4; nt++)
#pragma unroll
        for (int q = 0; q < 4; q++) acc[nt][q] = 0.f;

    auto stage = [&](int kt, int buf) {
        if (kt < 112) {
            const float* src = &g_h2[(m0 + mA) * 3600 + kt * 32 + kslA];
            unsigned d0 = sptr(&As[buf][mA * 36 + kslA]);
            CP_ASYNC16(d0, src);
            CP_ASYNC16(d0 + 16, src + 4);
        } else {
#pragma unroll
            for (int q = 0; q < 8; q++) {
                int k = 3584 + kslA + q;
                unsigned v = 0u;
                if (k < 3600) v = __float_as_uint(g_h2[(m0 + mA) * 3600 + k]);
                else if (k < 3602) v = f2tf(g_c[(m0 + mA) * 2 + (k - 3600)]);
                As[buf][mA * 36 + kslA + q] = v;
            }
        }
#pragma unroll
        for (int kk = 0; kk < 4; kk++)
            CP_ASYNC8(sptr(&Bsp[buf][(kgB * 4 + kk) * 65 + nB]),
                      &g_w1p[(((kt * 4 + kgB) * 4) + kk) * 512 + n0 + nB]);
        CP_COMMIT;
    };

    stage(0, 0);
    stage(1, 1);

    for (int kt = 0; kt < 113; kt++) {
        if (kt >= 111) { CP_WAIT(0); } else { CP_WAIT(1); }
        __syncthreads();
        int buf = kt & 1;
#pragma unroll
        for (int kc = 0; kc < 4; kc++) {
            unsigned a0 = As[buf][(ws * 16 + g) * 36 + kc * 8 + t];
            unsigned a1 = As[buf][(ws * 16 + g + 8) * 36 + kc * 8 + t];
            unsigned a2 = As[buf][(ws * 16 + g) * 36 + kc * 8 + t + 4];
            unsigned a3 = As[buf][(ws * 16 + g + 8) * 36 + kc * 8 + t + 4];
#pragma unroll
            for (int nt = 0; nt < 4; nt++) {
                uint2 bb = Bsp[buf][(kc * 4 + t) * 65 + wn + nt * 8 + g];
                mma8(acc[nt], a0, a1, a2, a3, bb.x, bb.y);
            }
        }
        __syncthreads();
        if (kt + 2 <= 112) stage(kt + 2, buf);
    }

    int mrow = m0 + ws * 16 + g;
#pragma unroll
    for (int nt = 0; nt < 4; nt++) {
        int n = n0 + wn + nt * 8 + 2 * t;
        if (n < 500) {
            float bv = bias[n];
            g_f1[mrow * 500 + n]       = fmaxf(acc[nt][0] + bv, 0.f);
            g_f1[(mrow + 8) * 500 + n] = fmaxf(acc[nt][2] + bv, 0.f);
        }
        if (n + 1 < 500) {
            float bv = bias[n + 1];
            g_f1[mrow * 500 + n + 1]       = fmaxf(acc[nt][1] + bv, 0.f);
            g_f1[(mrow + 8) * 500 + n + 1] = fmaxf(acc[nt][3] + bv, 0.f);
        }
    }
}

// ---------------- fc2: [f1 | y] @ W2^T + b2, one warp per (b,o) ----------------
__global__ __launch_bounds__(256) void fc2_k(
    const float* __restrict__ y, const float* __restrict__ w2,
    const float* __restrict__ b2, float* __restrict__ out) {
    int warp = (blockIdx.x * blockDim.x + threadIdx.x) >> 5;
    int lane = threadIdx.x & 31;
    int b = warp >> 1, o = warp & 1;
    const float* f1 = g_f1 + b * 500;
    const float* w = w2 + o * 502;
    float s = 0.f;
    for (int j = lane; j < 500; j += 32) s = fmaf(f1[j], w[j], s);
    if (lane == 0) s += w[500] * y[b * 2] + w[501] * y[b * 2 + 1] + b2[o];
#pragma unroll
    for (int off = 16; off; off >>= 1) s += __shfl_xor_sync(0xffffffffu, s, off);
    if (lane == 0) out[b * 2 + o] = s;
}

// ---------------- launch ----------------
extern "C" void kernel_launch(void* const* d_in, const int* in_sizes, int n_in,
                              void* d_out, int out_size) {
    const float* x   = (const float*)d_in[0];
    const float* y   = (const float*)d_in[1];
    const float* c1w = (const float*)d_in[2];
    const float* c1b = (const float*)d_in[3];
    const float* c2w = (const float*)d_in[4];
    const float* c2b = (const float*)d_in[5];
    const float* pw  = (const float*)d_in[6];
    const float* pb  = (const float*)d_in[7];
    const float* rw  = (const float*)d_in[8];
    const float* f1w = (const float*)d_in[9];
    const float* f1b = (const float*)d_in[10];
    const float* f2w = (const float*)d_in[11];
    const float* f2b = (const float*)d_in[12];
    float* out = (float*)d_out;

    const int bb_smem = 108864;
    cudaFuncSetAttribute(backbone_k, cudaFuncAttributeMaxDynamicSharedMemorySize, bb_smem);

    prep_k<<<512, 256>>>(c2w, pw, f1w);
    backbone_k<<<NB, 288, bb_smem>>>(x, c1w, c1b, c2b, pb, rw);
    dim3 g4(8, 32);
    fc1_mma_k<<<g4, 256>>>(f1b);
    fc2_k<<<NB * 2 / 8, 256>>>(y, f2w, f2b, out);
}

// round 5
// speedup vs baseline: 1.7586x; 1.0719x over previous
#include <cuda_runtime.h>
#include <math.h>
#include <stdint.h>

#define NB 2048

// ---------------- scratch (device globals; no allocation) ----------------
__device__ float g_h2[NB * 3600];           // conv2+pool out (tf32-rounded) [b][50][6][12]
__device__ float g_c [NB * 2];              // routed capsule outputs
__device__ float g_f1[NB * 500];            // fc1 relu out
__device__ uint2 g_w2f[64 * 4 * 64];        // conv2 B frags: [kc][kk][n] tf32 pairs {k,k+4}
__device__ uint4 g_wpa[160 * 32];           // pcaps A frags (tf32, per-lane a0..a3)
__device__ uint2 g_w1p[452 * 4 * 512];      // fc1 B frags: [kc][kk][n] tf32 pairs {k,k+4}
__device__ int2  g_koffc[256];              // conv2 im2col offsets {k,k+4}
__device__ int2  g_koffp[640];              // pcaps im2col offsets {k,k+4}

// ---------------- helpers ----------------
__device__ __forceinline__ unsigned f2tf(float f) {
    unsigned u; asm("cvt.rna.tf32.f32 %0, %1;" : "=r"(u) : "f"(f)); return u;
}
__device__ __forceinline__ void mma8(float* d, unsigned a0, unsigned a1, unsigned a2,
                                     unsigned a3, unsigned b0, unsigned b1) {
    asm volatile(
        "mma.sync.aligned.m16n8k8.row.col.f32.tf32.tf32.f32 "
        "{%0,%1,%2,%3},{%4,%5,%6,%7},{%8,%9},{%0,%1,%2,%3};"
        : "+f"(d[0]), "+f"(d[1]), "+f"(d[2]), "+f"(d[3])
        : "r"(a0), "r"(a1), "r"(a2), "r"(a3), "r"(b0), "r"(b1));
}
__device__ __forceinline__ unsigned sptr(const void* p) {
    return (unsigned)__cvta_generic_to_shared(p);
}
#define CP_ASYNC8(dst, src)  asm volatile("cp.async.ca.shared.global [%0], [%1], 8;"  :: "r"(dst), "l"(src))
#define CP_ASYNC16(dst, src) asm volatile("cp.async.cg.shared.global [%0], [%1], 16;" :: "r"(dst), "l"(src))
#define CP_COMMIT            asm volatile("cp.async.commit_group;")
#define CP_WAIT(n)           asm volatile("cp.async.wait_group %0;" :: "n"(n))

// ---------------- prep: weight fragment layouts + im2col offset tables ----------------
__global__ void prep_k(const float* __restrict__ w2, const float* __restrict__ pw,
                       const float* __restrict__ w1) {
    int gtid = blockIdx.x * blockDim.x + threadIdx.x;
    int stride = gridDim.x * blockDim.x;
    for (int i = gtid; i < 16384; i += stride) {   // conv2 B frags
        int kc = i >> 8, rem = i & 255, kk = rem >> 6, n = rem & 63;
        int k = kc * 8 + kk;
        float v0 = (n < 50 && k     < 500) ? w2[n * 500 + k]     : 0.f;
        float v1 = (n < 50 && k + 4 < 500) ? w2[n * 500 + k + 4] : 0.f;
        g_w2f[i] = make_uint2(f2tf(v0), f2tf(v1));
    }
    for (int i = gtid; i < 5120; i += stride) {    // pcaps A frags
        int kc = i >> 5, lane = i & 31, g = lane >> 2, t = lane & 3;
        int k0 = kc * 8;
        float v0 = (k0 + t     < 1250) ? pw[g * 1250 + k0 + t]           : 0.f;
        float v1 = (k0 + t     < 1250) ? pw[(g + 8) * 1250 + k0 + t]     : 0.f;
        float v2 = (k0 + t + 4 < 1250) ? pw[g * 1250 + k0 + t + 4]       : 0.f;
        float v3 = (k0 + t + 4 < 1250) ? pw[(g + 8) * 1250 + k0 + t + 4] : 0.f;
        g_wpa[i] = make_uint4(f2tf(v0), f2tf(v1), f2tf(v2), f2tf(v3));
    }
    for (int i = gtid; i < 256; i += stride) {     // conv2 offsets
        int k = (i >> 2) * 8 + (i & 3);
        int o0 = (k < 500) ? (k / 25) * 448 + ((k % 25) / 5) * 28 + (k % 5) : 8960;
        int k4 = k + 4;
        int o1 = (k4 < 500) ? (k4 / 25) * 448 + ((k4 % 25) / 5) * 28 + (k4 % 5) : 8960;
        g_koffc[i] = make_int2(o0, o1);
    }
    for (int i = gtid; i < 640; i += stride) {     // pcaps offsets
        int k = (i >> 2) * 8 + (i & 3);
        int o0 = (k < 1250) ? (k / 25) * 160 + ((k % 25) / 5) * 16 + (k % 5) : 8000;
        int k4 = k + 4;
        int o1 = (k4 < 1250) ? (k4 / 25) * 160 + ((k4 % 25) / 5) * 16 + (k4 % 5) : 8000;
        g_koffp[i] = make_int2(o0, o1);
    }
    for (int i = gtid; i < 452 * 4 * 512; i += stride) {  // fc1 B frags (K padded to 3616)
        int kc = i >> 11, rem = i & 2047, kk = rem >> 9, n = rem & 511;
        int k = kc * 8 + kk;
        float v0 = (n < 500 && k     < 3602) ? w1[n * 3602 + k]     : 0.f;
        float v1 = (n < 500 && k + 4 < 3602) ? w1[n * 3602 + k + 4] : 0.f;
        g_w1p[i] = make_uint2(f2tf(v0), f2tf(v1));
    }
}

// ================= fused backbone =================
// dyn smem (108864 B), phase-aliased:
//   [0      .. 37168)  sxt u32[9292]         | post-conv2 alias: sconv f32[14400] (..57600) | sp f32[1152]
//   [37184  .. 70464)  sBf0 uint2[4160]
//   [70464  ..103744)  sBf1 uint2[4160]      | phase0 alias: sx1 f32[2160] | post-conv2 alias: sh2p u32[8096]
//   [103744 ..108864)  skoffp int2[640]
__device__ __forceinline__ float sq1(float s) { return s * fabsf(s) / (1.f + s * s); }

__global__ __launch_bounds__(288, 2) void backbone_k(
    const float* __restrict__ x, const float* __restrict__ c1w, const float* __restrict__ c1b,
    const float* __restrict__ c2b, const float* __restrict__ pcb, const float* __restrict__ rw) {
    extern __shared__ __align__(16) unsigned char cs[];
    unsigned* sxt    = (unsigned*)cs;
    uint2*    sBf0   = (uint2*)(cs + 37184);
    uint2*    sBf1   = (uint2*)(cs + 70464);
    float*    sconv  = (float*)cs;
    float*    sp     = (float*)cs;
    float*    sx1    = (float*)(cs + 70464);
    unsigned* sh2p   = (unsigned*)(cs + 70464);
    int2*     skoffp = (int2*)(cs + 103744);
    __shared__ float sw1[500];
    __shared__ float sb1[20];
    __shared__ int2  skoffc[256];

    int b = blockIdx.x, tid = threadIdx.x;
    int warp = tid >> 5, lane = tid & 31, g = lane >> 2, t = lane & 3;

    // ---- P0 ----
    for (int i = tid; i < 2160; i += 288) sx1[i] = x[b * 2160 + i];
    for (int i = tid; i < 500;  i += 288) sw1[i] = c1w[i];
    if (tid < 20) sb1[tid] = c1b[tid];
    for (int i = tid; i < 256; i += 288) skoffc[i] = g_koffc[i];
    for (int i = tid; i < 640; i += 288) skoffp[i] = g_koffp[i];
    __syncthreads();

    // prefetch conv2 B window 0 (hidden behind conv1)
    for (int i = tid; i < 4096; i += 288) {
        int row = i >> 6, n = i & 63;
        CP_ASYNC8(sptr(&sBf0[row * 65 + n]), &g_w2f[i]);
    }
    CP_COMMIT;

    // ---- conv1 + pool (exact fp32): one patch per item serves 4 ocs ----
    for (int i = tid; i < 2240; i += 288) {
        int og = i / 448, pos = i % 448;
        int ph = pos / 28, pw = pos % 28;
        int r0 = ph * 2, c0 = pw * 2;
        float patch[6][6];
#pragma unroll
        for (int pr = 0; pr < 6; pr++) {
            const float2* row = (const float2*)&sx1[(r0 + pr) * 60 + c0];
            float2 p0 = row[0], p1 = row[1], p2 = row[2];
            patch[pr][0] = p0.x; patch[pr][1] = p0.y;
            patch[pr][2] = p1.x; patch[pr][3] = p1.y;
            patch[pr][4] = p2.x; patch[pr][5] = p2.y;
        }
        int oc0 = og * 4;
#pragma unroll
        for (int o = 0; o < 4; o++) {
            const float* wp = &sw1[(oc0 + o) * 25];
            float a00 = 0, a01 = 0, a10 = 0, a11 = 0;
#pragma unroll
            for (int kr = 0; kr < 5; kr++)
#pragma unroll
                for (int kc = 0; kc < 5; kc++) {
                    float wv = wp[kr * 5 + kc];
                    a00 = fmaf(patch[kr][kc],         wv, a00);
                    a01 = fmaf(patch[kr][kc + 1],     wv, a01);
                    a10 = fmaf(patch[kr + 1][kc],     wv, a10);
                    a11 = fmaf(patch[kr + 1][kc + 1], wv, a11);
                }
            sxt[(oc0 + o) * 448 + pos] =
                f2tf(fmaxf(fmaxf(a00, a01), fmaxf(a10, a11)) + sb1[oc0 + o]);
        }
    }
    for (int i = 8960 + tid; i < 9292; i += 288) sxt[i] = 0u;
    __syncthreads();   // conv1 done; sx1 dead

    // prefetch window 1 into sBf1 (sx1 region now dead)
    for (int i = tid; i < 4096; i += 288) {
        int row = i >> 6, n = i & 63;
        CP_ASYNC8(sptr(&sBf1[row * 65 + n]), &g_w2f[4096 + i]);
    }
    CP_COMMIT;
    CP_WAIT(1);
    __syncthreads();   // window 0 visible

    // ---- conv2 via tf32 mma: M=288, N=56(50), K=512(500), double-buffered B ----
    float acc[2][7][4];
#pragma unroll
    for (int s = 0; s < 2; s++)
#pragma unroll
        for (int nt = 0; nt < 7; nt++)
#pragma unroll
            for (int q = 0; q < 4; q++) acc[s][nt][q] = 0.f;

    int pb[2][2];
#pragma unroll
    for (int s = 0; s < 2; s++) {
        int m0 = (warp * 2 + s) * 16 + g;
        pb[s][0] = (m0 / 24) * 28 + (m0 % 24);
        int m1 = m0 + 8;
        pb[s][1] = (m1 / 24) * 28 + (m1 % 24);
    }

    for (int win = 0; win < 4; win++) {
        uint2* sBf = (win & 1) ? sBf1 : sBf0;
#pragma unroll 4
        for (int wk = 0; wk < 16; wk++) {
            int2 ko = skoffc[(win * 16 + wk) * 4 + t];
            unsigned a[2][4];
#pragma unroll
            for (int s = 0; s < 2; s++) {
                a[s][0] = sxt[pb[s][0] + ko.x];
                a[s][1] = sxt[pb[s][1] + ko.x];
                a[s][2] = sxt[pb[s][0] + ko.y];
                a[s][3] = sxt[pb[s][1] + ko.y];
            }
#pragma unroll
            for (int nt = 0; nt < 7; nt++) {
                uint2 bb = sBf[(wk * 4 + t) * 65 + nt * 8 + g];
                mma8(acc[0][nt], a[0][0], a[0][1], a[0][2], a[0][3], bb.x, bb.y);
                mma8(acc[1][nt], a[1][0], a[1][1], a[1][2], a[1][3], bb.x, bb.y);
            }
        }
        __syncthreads();   // done reading this buffer
        if (win < 2) {
            for (int i = tid; i < 4096; i += 288) {
                int row = i >> 6, n = i & 63;
                CP_ASYNC8(sptr(&sBf[row * 65 + n]), &g_w2f[(win + 2) * 4096 + i]);
            }
            CP_COMMIT;
            CP_WAIT(1);
        } else {
            CP_WAIT(0);
        }
        __syncthreads();   // next buffer visible
    }

    // ---- writeout conv2 pre-pool (sconv aliases sxt/sBf0) + zero pcaps buffer ----
#pragma unroll
    for (int s = 0; s < 2; s++) {
        int m0 = (warp * 2 + s) * 16 + g;
#pragma unroll
        for (int nt = 0; nt < 7; nt++) {
            int n0 = nt * 8 + 2 * t;
            if (n0 < 50) {
                sconv[n0 * 288 + m0]     = acc[s][nt][0];
                sconv[n0 * 288 + m0 + 8] = acc[s][nt][2];
            }
            if (n0 + 1 < 50) {
                sconv[(n0 + 1) * 288 + m0]     = acc[s][nt][1];
                sconv[(n0 + 1) * 288 + m0 + 8] = acc[s][nt][3];
            }
        }
    }
    for (int i = tid; i < 8096; i += 288) sh2p[i] = 0u;
    __syncthreads();

    // ---- maxpool + bias -> tf32; padded smem + g_h2 ----
    for (int i = tid; i < 3600; i += 288) {
        int oc = i / 72, rem = i % 72, ph = rem / 12, pw = rem % 12;
        const float* base = &sconv[oc * 288 + ph * 48 + pw * 2];
        float m = fmaxf(fmaxf(base[0], base[1]), fmaxf(base[24], base[25])) + c2b[oc];
        unsigned r = f2tf(m);
        sh2p[oc * 160 + (ph + 2) * 16 + (pw + 2)] = r;
        g_h2[b * 3600 + i] = __uint_as_float(r);
    }
    __syncthreads();

    // ---- pcaps via tf32 mma, 4 independent acc chains + 1-iter prefetch ----
    {
        int nt = warp;
        int p = nt * 8 + g;
        int pbase = (p / 12) * 16 + (p % 12);
        float pa4[4][4];
#pragma unroll
        for (int c = 0; c < 4; c++)
#pragma unroll
            for (int q = 0; q < 4; q++) pa4[c][q] = 0.f;

        uint4 aa = g_wpa[lane];
        int2 ko = skoffp[t];
        unsigned b0 = sh2p[ko.x + pbase];
        unsigned b1 = sh2p[ko.y + pbase];
#pragma unroll 4
        for (int kc = 0; kc < 160; kc++) {
            uint4 aan; int2 kon; unsigned b0n, b1n;
            if (kc < 159) {
                aan = g_wpa[(kc + 1) * 32 + lane];
                kon = skoffp[(kc + 1) * 4 + t];
                b0n = sh2p[kon.x + pbase];
                b1n = sh2p[kon.y + pbase];
            }
            mma8(pa4[kc & 3], aa.x, aa.y, aa.z, aa.w, b0, b1);
            if (kc < 159) { aa = aan; ko = kon; b0 = b0n; b1 = b1n; }
        }
        float pa[4];
#pragma unroll
        for (int q = 0; q < 4; q++)
            pa[q] = (pa4[0][q] + pa4[1][q]) + (pa4[2][q] + pa4[3][q]);

        __syncthreads();   // sconv dead; sp writes begin
        int oc0 = g;
        int n0 = nt * 8 + 2 * t;
        float bsA = pcb[oc0], bsB = pcb[oc0 + 8];
        sp[oc0 * 72 + n0]           = pa[0] + bsA;
        sp[oc0 * 72 + n0 + 1]       = pa[1] + bsA;
        sp[(oc0 + 8) * 72 + n0]     = pa[2] + bsB;
        sp[(oc0 + 8) * 72 + n0 + 1] = pa[3] + bsB;
    }
    __syncthreads();

    // ---- squash + priors + 3-iter routing: warps 0,1 ----
    if (warp < 2) {
        int k = warp;
        float pr[9];
#pragma unroll
        for (int j = 0; j < 9; j++) {
            int r = lane + 32 * j;
            int cw = r / 72, hw = r % 72;
            const float* pbp = sp + cw * 72 + hw;
            float u0 = pbp[0], u1 = pbp[288], u2 = pbp[576], u3 = pbp[864];
            float n2 = u0 * u0 + u1 * u1 + u2 * u2 + u3 * u3;
            float f = sqrtf(n2) / (1.f + n2);
            float4 w4 = *(const float4*)&rw[(k * 288 + r) * 4];
            pr[j] = f * (u0 * w4.x + u1 * w4.y + u2 * w4.z + u3 * w4.w);
        }
        float S = 0.f;
#pragma unroll
        for (int j = 0; j < 9; j++) S += pr[j];
#pragma unroll
        for (int o = 16; o; o >>= 1) S += __shfl_xor_sync(0xffffffffu, S, o);
        float s = S * (1.f / 288.f);
        float v = sq1(s);
        float vsum = v;
#pragma unroll
        for (int it = 0; it < 2; it++) {
            float m = -1e30f;
#pragma unroll
            for (int j = 0; j < 9; j++) m = fmaxf(m, pr[j] * vsum);
#pragma unroll
            for (int o = 16; o; o >>= 1) m = fmaxf(m, __shfl_xor_sync(0xffffffffu, m, o));
            float Z = 0.f, T = 0.f;
#pragma unroll
            for (int j = 0; j < 9; j++) {
                float e = __expf(pr[j] * vsum - m);
                Z += e;
                T = fmaf(e, pr[j], T);
            }
#pragma unroll
            for (int o = 16; o; o >>= 1) {
                Z += __shfl_xor_sync(0xffffffffu, Z, o);
                T += __shfl_xor_sync(0xffffffffu, T, o);
            }
            float s2 = T / Z;
            v = sq1(s2);
            vsum += v;
        }
        if (lane == 0) g_c[b * 2 + k] = v;
    }
}

// ---------------- fc1: M=2048, N=512(500), K=3616(3602); 64x64 tiles, cp.async 3-stage ----------------
__global__ __launch_bounds__(256) void fc1_mma_k(const float* __restrict__ bias) {
    __shared__ __align__(16) unsigned As[3][64 * 36];
    __shared__ __align__(16) uint2 Bsp[3][16 * 65 + 8];
    int m0 = blockIdx.y * 64, n0 = blockIdx.x * 64;
    int tid = threadIdx.x, warp = tid >> 5, lane = tid & 31, g = lane >> 2, t = lane & 3;
    int ws = warp & 3;            // m strip
    int wn = (warp >> 2) * 32;    // n offset
    int mA = tid & 63, kslA = (tid >> 6) * 8;
    int nB = tid & 63, kgB = tid >> 6;

    float acc[4][4];
#pragma unroll
    for (int nt = 0; nt < 4; nt++)
#pragma unroll
        for (int q = 0; q < 4; q++) acc[nt][q] = 0.f;

    auto stage = [&](int kt, int buf) {
        if (kt < 112) {
            const float* src = &g_h2[(m0 + mA) * 3600 + kt * 32 + kslA];
            unsigned d0 = sptr(&As[buf][mA * 36 + kslA]);
            CP_ASYNC16(d0, src);
            CP_ASYNC16(d0 + 16, src + 4);
        } else {
#pragma unroll
            for (int q = 0; q < 8; q++) {
                int k = 3584 + kslA + q;
                unsigned v = 0u;
                if (k < 3600) v = __float_as_uint(g_h2[(m0 + mA) * 3600 + k]);
                else if (k < 3602) v = f2tf(g_c[(m0 + mA) * 2 + (k - 3600)]);
                As[buf][mA * 36 + kslA + q] = v;
            }
        }
#pragma unroll
        for (int kk = 0; kk < 4; kk++)
            CP_ASYNC8(sptr(&Bsp[buf][(kgB * 4 + kk) * 65 + nB]),
                      &g_w1p[(((kt * 4 + kgB) * 4) + kk) * 512 + n0 + nB]);
        CP_COMMIT;
    };

    stage(0, 0);
    stage(1, 1);
    stage(2, 2);

    int buf = 0;
    for (int kt = 0; kt < 113; kt++) {
        if (kt < 111) { CP_WAIT(2); }
        else if (kt == 111) { CP_WAIT(1); }
        else { CP_WAIT(0); }
        __syncthreads();
#pragma unroll
        for (int kc = 0; kc < 4; kc++) {
            unsigned a0 = As[buf][(ws * 16 + g) * 36 + kc * 8 + t];
            unsigned a1 = As[buf][(ws * 16 + g + 8) * 36 + kc * 8 + t];
            unsigned a2 = As[buf][(ws * 16 + g) * 36 + kc * 8 + t + 4];
            unsigned a3 = As[buf][(ws * 16 + g + 8) * 36 + kc * 8 + t + 4];
#pragma unroll
            for (int nt = 0; nt < 4; nt++) {
                uint2 bb = Bsp[buf][(kc * 4 + t) * 65 + wn + nt * 8 + g];
                mma8(acc[nt], a0, a1, a2, a3, bb.x, bb.y);
            }
        }
        __syncthreads();
        if (kt + 3 <= 112) stage(kt + 3, buf);
        buf = (buf == 2) ? 0 : buf + 1;
    }

    int mrow = m0 + ws * 16 + g;
#pragma unroll
    for (int nt = 0; nt < 4; nt++) {
        int n = n0 + wn + nt * 8 + 2 * t;
        if (n < 500) {
            float bv = bias[n];
            g_f1[mrow * 500 + n]       = fmaxf(acc[nt][0] + bv, 0.f);
            g_f1[(mrow + 8) * 500 + n] = fmaxf(acc[nt][2] + bv, 0.f);
        }
        if (n + 1 < 500) {
            float bv = bias[n + 1];
            g_f1[mrow * 500 + n + 1]       = fmaxf(acc[nt][1] + bv, 0.f);
            g_f1[(mrow + 8) * 500 + n + 1] = fmaxf(acc[nt][3] + bv, 0.f);
        }
    }
}

// ---------------- fc2: [f1 | y] @ W2^T + b2, one warp per (b,o) ----------------
__global__ __launch_bounds__(256) void fc2_k(
    const float* __restrict__ y, const float* __restrict__ w2,
    const float* __restrict__ b2, float* __restrict__ out) {
    int warp = (blockIdx.x * blockDim.x + threadIdx.x) >> 5;
    int lane = threadIdx.x & 31;
    int b = warp >> 1, o = warp & 1;
    const float* f1 = g_f1 + b * 500;
    const float* w = w2 + o * 502;
    float s = 0.f;
    for (int j = lane; j < 500; j += 32) s = fmaf(f1[j], w[j], s);
    if (lane == 0) s += w[500] * y[b * 2] + w[501] * y[b * 2 + 1] + b2[o];
#pragma unroll
    for (int off = 16; off; off >>= 1) s += __shfl_xor_sync(0xffffffffu, s, off);
    if (lane == 0) out[b * 2 + o] = s;
}

// ---------------- launch ----------------
extern "C" void kernel_launch(void* const* d_in, const int* in_sizes, int n_in,
                              void* d_out, int out_size) {
    const float* x   = (const float*)d_in[0];
    const float* y   = (const float*)d_in[1];
    const float* c1w = (const float*)d_in[2];
    const float* c1b = (const float*)d_in[3];
    const float* c2w = (const float*)d_in[4];
    const float* c2b = (const float*)d_in[5];
    const float* pw  = (const float*)d_in[6];
    const float* pb  = (const float*)d_in[7];
    const float* rw  = (const float*)d_in[8];
    const float* f1w = (const float*)d_in[9];
    const float* f1b = (const float*)d_in[10];
    const float* f2w = (const float*)d_in[11];
    const float* f2b = (const float*)d_in[12];
    float* out = (float*)d_out;

    const int bb_smem = 108864;
    cudaFuncSetAttribute(backbone_k, cudaFuncAttributeMaxDynamicSharedMemorySize, bb_smem);

    prep_k<<<512, 256>>>(c2w, pw, f1w);
    backbone_k<<<NB, 288, bb_smem>>>(x, c1w, c1b, c2b, pb, rw);
    dim3 g4(8, 32);
    fc1_mma_k<<<g4, 256>>>(f1b);
    fc2_k<<<NB * 2 / 8, 256>>>(y, f2w, f2b, out);
}